// round 3
// baseline (speedup 1.0000x reference)
#include <cuda_runtime.h>
#include <math.h>

// ---------------------------------------------------------------------------
// Problem: B=128, C=320, N=256 (=16x16), GROUPS=5 (64 ch/group), RATIO=8
#define SZ 10485760   // 128*320*256
__device__ float g_bands[2][SZ];     // low, mid bands (high = x - low - mid)
__device__ float g_feat[3][SZ];      // per-band conv+GN+residual features
__device__ float g_avg[40960];       // [B][C] channel means
__device__ float g_cw[128 * 960];    // [B][3*C] channel-attention weights
__device__ float g_kappa[2][256];    // circular-conv kernels for low/mid masks

// ---- packed f32x2 helpers (Blackwell FFMA2 path; ptxas never emits these) --
__device__ __forceinline__ unsigned long long f2pack(float lo, float hi) {
    unsigned long long r;
    asm("mov.b64 %0, {%1, %2};" : "=l"(r) : "f"(lo), "f"(hi));
    return r;
}
__device__ __forceinline__ void f2unpack(unsigned long long v, float& lo, float& hi) {
    asm("mov.b64 {%0, %1}, %2;" : "=f"(lo), "=f"(hi) : "l"(v));
}
__device__ __forceinline__ unsigned long long ffma2(unsigned long long a,
                                                    unsigned long long b,
                                                    unsigned long long c) {
    unsigned long long d;
    asm("fma.rn.f32x2 %0, %1, %2, %3;" : "=l"(d) : "l"(a), "l"(b), "l"(c));
    return d;
}

// ---------------------------------------------------------------------------
// Kernel 1: per-(b,c) mean over N=256.  grid (128, 40), block 256 (8 warps)
__global__ void k_avg(const float* __restrict__ x) {
    int b = blockIdx.x;
    int c = blockIdx.y * 8 + (threadIdx.x >> 5);
    int lane = threadIdx.x & 31;
    const float* px = x + ((size_t)b * 320 + c) * 256;
    float s = 0.f;
#pragma unroll
    for (int i = 0; i < 8; i++) s += px[lane + 32 * i];
#pragma unroll
    for (int o = 16; o > 0; o >>= 1) s += __shfl_xor_sync(0xffffffffu, s, o);
    if (lane == 0) g_avg[b * 320 + c] = s * (1.0f / 256.0f);
}

// ---------------------------------------------------------------------------
// Kernel 2: channel attention MLP.  grid 128 (one per b), block 256.
__global__ void k_ca(const float* __restrict__ w1, const float* __restrict__ b1,
                     const float* __restrict__ w2, const float* __restrict__ b2) {
    __shared__ float av[320];
    __shared__ float hs[40];
    int b = blockIdx.x, tid = threadIdx.x;
    for (int e = tid; e < 320; e += 256) av[e] = g_avg[b * 320 + e];
    __syncthreads();
    if (tid < 40) {
        float s = b1[tid];
        for (int c = 0; c < 320; c++) s += av[c] * w1[tid * 320 + c];
        hs[tid] = fmaxf(s, 0.0f);
    }
    __syncthreads();
    for (int o = tid; o < 960; o += 256) {
        float s = b2[o];
#pragma unroll
        for (int k = 0; k < 40; k++) s += hs[k] * w2[o * 40 + k];
        g_cw[b * 960 + o] = 1.0f / (1.0f + expf(-s));
    }
}

// ---------------------------------------------------------------------------
// Kernel 3: build circular-conv kernels kappa[m] from the masks (JAX-exact fp32).
__device__ __forceinline__ float jsig(float z) { return 1.0f / (1.0f + expf(-z)); }

__global__ void k_prep(const float* __restrict__ lcp, const float* __restrict__ hcp) {
    __shared__ double ctab[16];
    int t = threadIdx.x;
    if (t < 16) ctab[t] = cos((double)t * 3.14159265358979323846 / 8.0);
    __syncthreads();
    float lc = *lcp, hc = *hcp;
    int a = t >> 4, bb = t & 15;
    float step = __fdiv_rn(2.0f, 15.0f);
    for (int m = 0; m < 2; m++) {
        double acc = 0.0;
        for (int u = 0; u < 16; u++) {
            int s = (u + 8) & 15;
            float yv = __fadd_rn(__fmul_rn((float)s, step), -1.0f);
            for (int v = 0; v < 16; v++) {
                int t2 = (v + 8) & 15;
                float xv = __fadd_rn(__fmul_rn((float)t2, step), -1.0f);
                float d2 = __fadd_rn(__fmul_rn(xv, xv), __fmul_rn(yv, yv));
                float d = __fdiv_rn(__fsqrt_rn(d2), 1.4142135623730951f);
                float mv;
                if (m == 0) {
                    mv = jsig(__fdiv_rn(__fsub_rn(lc, d), 1e-6f));
                } else {
                    float m1 = jsig(__fdiv_rn(__fsub_rn(d, lc), 1e-6f));
                    float m2 = jsig(__fdiv_rn(__fsub_rn(hc, d), 1e-6f));
                    mv = m1 * m2;
                }
                int ph = (u * a + v * bb) & 15;
                acc += (double)mv * ctab[ph];
            }
        }
        g_kappa[m][t] = (float)(acc * (1.0 / 256.0));
    }
}

// ---------------------------------------------------------------------------
// Kernel 4: band GEMM with FFMA2.  out[m][row][p] = sum_q x[row][q]*kappa[idx(p,q)]
__global__ __launch_bounds__(256) void k_band(const float* __restrict__ x) {
    __shared__ float As[64][32];
    __shared__ float Bs[32][256];
    __shared__ float ks[256];
    int m = blockIdx.y;
    int rows0 = blockIdx.x * 64;
    int tid = threadIdx.x;
    ks[tid] = g_kappa[m][tid];
    int tr = tid >> 5, tp = tid & 31;
    unsigned long long acc2[4][8];   // row-pairs (i=2pr, 2pr+1) x 8 cols
#pragma unroll
    for (int pr = 0; pr < 4; pr++)
#pragma unroll
        for (int j = 0; j < 8; j++) acc2[pr][j] = 0ull;
    int rl = tid >> 2, qo = (tid & 3) * 8;
    for (int kq = 0; kq < 256; kq += 32) {
        __syncthreads();
        const float4* src = (const float4*)(x + (size_t)(rows0 + rl) * 256 + kq + qo);
        float4 a0 = src[0], a1 = src[1];
        *((float4*)&As[rl][qo])     = a0;
        *((float4*)&As[rl][qo + 4]) = a1;
#pragma unroll
        for (int it = 0; it < 32; it++) {
            int q = kq + it, p = tid;
            int aa = ((p >> 4) - (q >> 4)) & 15;
            int bbq = ((p & 15) - (q & 15)) & 15;
            Bs[it][p] = ks[aa * 16 + bbq];
        }
        __syncthreads();
#pragma unroll
        for (int ql = 0; ql < 32; ql++) {
            unsigned long long av2[4], bv2[8];
#pragma unroll
            for (int pr = 0; pr < 4; pr++)
                av2[pr] = f2pack(As[tr * 8 + 2 * pr][ql], As[tr * 8 + 2 * pr + 1][ql]);
#pragma unroll
            for (int j = 0; j < 8; j++) {
                float bv = Bs[ql][tp + 32 * j];
                bv2[j] = f2pack(bv, bv);
            }
#pragma unroll
            for (int pr = 0; pr < 4; pr++)
#pragma unroll
                for (int j = 0; j < 8; j++)
                    acc2[pr][j] = ffma2(av2[pr], bv2[j], acc2[pr][j]);
        }
    }
    float* outp = g_bands[m];
#pragma unroll
    for (int pr = 0; pr < 4; pr++) {
        size_t r0 = (size_t)(rows0 + tr * 8 + 2 * pr) * 256;
        size_t r1 = r0 + 256;
#pragma unroll
        for (int j = 0; j < 8; j++) {
            float lo, hi;
            f2unpack(acc2[pr][j], lo, hi);
            outp[r0 + tp + 32 * j] = lo;
            outp[r1 + tp + 32 * j] = hi;
        }
    }
}

// ---------------------------------------------------------------------------
// Kernel 5: 3x3 conv + bias + GroupNorm + affine + residual, FFMA2 mainloop.
// grid (5 groups, 128 b, 3 bands), block 256.
// Block tile: 64 out-channels (== one GN group) x 256 pixels of one image.
// Thread tile: 8 co (as 4 packed pairs) x 8 px (half a pixel row).
__global__ __launch_bounds__(256, 2) void k_conv(
    const float* __restrict__ x,
    const float* __restrict__ wl, const float* __restrict__ bl,
    const float* __restrict__ gl, const float* __restrict__ el,
    const float* __restrict__ wm, const float* __restrict__ bm,
    const float* __restrict__ gm, const float* __restrict__ em,
    const float* __restrict__ wh, const float* __restrict__ bh,
    const float* __restrict__ gh, const float* __restrict__ eh) {
    __shared__ float in_s[8][18][19];   // padded 16x16 + halo, pitch 19 (bank-safe)
    __shared__ float w_s[8][9][64];     // [ci][tap][co]; co-pairs contiguous
    __shared__ float red_s[256];
    __shared__ float red_q[256];
    __shared__ float stats[2];

    int g = blockIdx.x, b = blockIdx.y, m = blockIdx.z;
    const float *W, *bias, *gam, *bet;
    if (m == 0)      { W = wl; bias = bl; gam = gl; bet = el; }
    else if (m == 1) { W = wm; bias = bm; gam = gm; bet = em; }
    else             { W = wh; bias = bh; gam = gh; bet = eh; }

    int tid = threadIdx.x;
    int tr = tid >> 5;          // co sub-tile: channels tr*8..tr*8+7 (warp-uniform)
    int tc = tid & 31;
    int r  = tc >> 1;           // pixel row 0..15
    int x0 = (tc & 1) * 8;      // pixel col base 0 or 8

    for (int e = tid; e < 8 * 18 * 19; e += 256) ((float*)in_s)[e] = 0.0f;

    unsigned long long acc2[4][8];   // co-pairs x 8 px
#pragma unroll
    for (int pr = 0; pr < 4; pr++)
#pragma unroll
        for (int px = 0; px < 8; px++) acc2[pr][px] = 0ull;

    const size_t base_in = (size_t)b * 81920;
    const float* band0 = g_bands[0];
    const float* band1 = g_bands[1];

    for (int cc = 0; cc < 40; cc++) {           // 40 chunks of 8 input channels
        __syncthreads();
#pragma unroll
        for (int it = 0; it < 8; it++) {        // load 8x256 inputs
            int cl = it, p = tid;
            size_t off = base_in + (size_t)(cc * 8 + cl) * 256 + p;
            float v;
            if (m == 0)      v = band0[off];
            else if (m == 1) v = band1[off];
            else             v = x[off] - band0[off] - band1[off];
            in_s[cl][1 + (p >> 4)][1 + (p & 15)] = v;
        }
#pragma unroll
        for (int it = 0; it < 18; it++) {       // load 64co x 8ci x 9 weights
            int e = tid + 256 * it;
            int co = e / 72, rem = e % 72;
            int cl = rem / 9, k = rem % 9;
            w_s[cl][k][co] = W[(size_t)(g * 64 + co) * 2880 + (cc * 8 + cl) * 9 + k];
        }
        __syncthreads();
#pragma unroll
        for (int cl = 0; cl < 8; cl++) {
#pragma unroll
            for (int ky = 0; ky < 3; ky++) {
                // one input row for this tap row; broadcast-pack each pixel
                unsigned long long rin2[10];
#pragma unroll
                for (int dx = 0; dx < 10; dx++) {
                    float rv = in_s[cl][r + ky][x0 + dx];
                    rin2[dx] = f2pack(rv, rv);
                }
#pragma unroll
                for (int kx = 0; kx < 3; kx++) {
                    // co-pairs straight out of shared as 64-bit values
                    const ulonglong2* wp =
                        (const ulonglong2*)&w_s[cl][ky * 3 + kx][tr * 8];
                    ulonglong2 wa = wp[0], wb = wp[1];
                    unsigned long long w2[4] = {wa.x, wa.y, wb.x, wb.y};
#pragma unroll
                    for (int pr = 0; pr < 4; pr++)
#pragma unroll
                        for (int px = 0; px < 8; px++)
                            acc2[pr][px] = ffma2(w2[pr], rin2[px + kx], acc2[pr][px]);
                }
            }
        }
    }
    // unpack accumulators, add bias (before GN stats, matching reference)
    float acc[8][8];
#pragma unroll
    for (int pr = 0; pr < 4; pr++)
#pragma unroll
        for (int px = 0; px < 8; px++)
            f2unpack(acc2[pr][px], acc[2 * pr][px], acc[2 * pr + 1][px]);
#pragma unroll
    for (int ci = 0; ci < 8; ci++) {
        float bv = bias[g * 64 + tr * 8 + ci];
#pragma unroll
        for (int px = 0; px < 8; px++) acc[ci][px] += bv;
    }
    // GroupNorm over exactly this block's 64ch x 256px
    float s = 0.f, q = 0.f;
#pragma unroll
    for (int ci = 0; ci < 8; ci++)
#pragma unroll
        for (int px = 0; px < 8; px++) { float v = acc[ci][px]; s += v; q += v * v; }
    red_s[tid] = s; red_q[tid] = q;
    __syncthreads();
    for (int off = 128; off > 0; off >>= 1) {
        if (tid < off) { red_s[tid] += red_s[tid + off]; red_q[tid] += red_q[tid + off]; }
        __syncthreads();
    }
    if (tid == 0) {
        float mu  = red_s[0] * (1.0f / 16384.0f);
        float var = red_q[0] * (1.0f / 16384.0f) - mu * mu;
        stats[0] = mu;
        stats[1] = rsqrtf(var + 1e-5f);
    }
    __syncthreads();
    float mu = stats[0], rs = stats[1];
    float* feat = g_feat[m];
#pragma unroll
    for (int ci = 0; ci < 8; ci++) {
        int c = g * 64 + tr * 8 + ci;
        float ga = gam[c], be = bet[c];
        size_t o = base_in + (size_t)c * 256 + r * 16 + x0;
#pragma unroll
        for (int px = 0; px < 8; px++)
            feat[o + px] = (acc[ci][px] - mu) * rs * ga + be + x[o + px];
    }
}

// ---------------------------------------------------------------------------
// Kernel 6: fused = sum_m cw_m*feat_m; sw = sigmoid(<fused, sa_w> + sa_b);
// out = fused * sw.  grid 128 (b), block 256 (one thread per pixel).
__global__ void k_fuse(const float* __restrict__ saw, const float* __restrict__ sab,
                       float* __restrict__ out) {
    __shared__ float cw_s[960];
    __shared__ float saw_s[320];
    int b = blockIdx.x, p = threadIdx.x;
    for (int e = p; e < 960; e += 256) cw_s[e] = g_cw[b * 960 + e];
    for (int e = p; e < 320; e += 256) saw_s[e] = saw[e];
    __syncthreads();
    size_t base = (size_t)b * 81920 + p;
    float sacc = 0.f;
    for (int c = 0; c < 320; c++) {
        size_t o = base + (size_t)c * 256;
        float f = cw_s[c] * g_feat[0][o] + cw_s[320 + c] * g_feat[1][o]
                + cw_s[640 + c] * g_feat[2][o];
        sacc += f * saw_s[c];
    }
    float sw = 1.0f / (1.0f + expf(-(sacc + sab[0])));
    for (int c = 0; c < 320; c++) {
        size_t o = base + (size_t)c * 256;
        float f = cw_s[c] * g_feat[0][o] + cw_s[320 + c] * g_feat[1][o]
                + cw_s[640 + c] * g_feat[2][o];
        out[o] = f * sw;
    }
}

// ---------------------------------------------------------------------------
extern "C" void kernel_launch(void* const* d_in, const int* in_sizes, int n_in,
                              void* d_out, int out_size) {
    const float* x   = (const float*)d_in[0];
    const float* lc  = (const float*)d_in[1];
    const float* hc  = (const float*)d_in[2];
    const float* w1  = (const float*)d_in[3];
    const float* b1  = (const float*)d_in[4];
    const float* w2  = (const float*)d_in[5];
    const float* b2  = (const float*)d_in[6];
    const float* wl  = (const float*)d_in[7];
    const float* bl  = (const float*)d_in[8];
    const float* gl  = (const float*)d_in[9];
    const float* el  = (const float*)d_in[10];
    const float* wm  = (const float*)d_in[11];
    const float* bm  = (const float*)d_in[12];
    const float* gm  = (const float*)d_in[13];
    const float* em  = (const float*)d_in[14];
    const float* wh  = (const float*)d_in[15];
    const float* bh  = (const float*)d_in[16];
    const float* gh  = (const float*)d_in[17];
    const float* eh  = (const float*)d_in[18];
    const float* saw = (const float*)d_in[19];
    const float* sab = (const float*)d_in[20];
    float* out = (float*)d_out;

    k_avg <<<dim3(128, 40), 256>>>(x);
    k_ca  <<<128, 256>>>(w1, b1, w2, b2);
    k_prep<<<1, 256>>>(lc, hc);
    k_band<<<dim3(640, 2), 256>>>(x);
    k_conv<<<dim3(5, 128, 3), 256>>>(x, wl, bl, gl, el, wm, bm, gm, em, wh, bh, gh, eh);
    k_fuse<<<128, 256>>>(saw, sab, out);
}

// round 4
// speedup vs baseline: 1.0055x; 1.0055x over previous
#include <cuda_runtime.h>
#include <math.h>

// ---------------------------------------------------------------------------
// Problem: B=128, C=320, N=256 (=16x16), GROUPS=5 (64 ch/group), RATIO=8
#define SZ 10485760   // 128*320*256
__device__ float g_bands[2][SZ];     // low, mid bands (high = x - low - mid)
__device__ float g_feat[3][SZ];      // per-band conv+GN+residual features
__device__ float g_avg[40960];       // [B][C] channel means
__device__ float g_cw[128 * 960];    // [B][3*C] channel-attention weights
__device__ float g_kappa[2][256];    // circular-conv kernels for low/mid masks

// ---- packed f32x2 helpers (Blackwell FFMA2 path; ptxas never emits these) --
__device__ __forceinline__ unsigned long long f2pack(float lo, float hi) {
    unsigned long long r;
    asm("mov.b64 %0, {%1, %2};" : "=l"(r) : "f"(lo), "f"(hi));
    return r;
}
__device__ __forceinline__ void f2unpack(unsigned long long v, float& lo, float& hi) {
    asm("mov.b64 {%0, %1}, %2;" : "=f"(lo), "=f"(hi) : "l"(v));
}
__device__ __forceinline__ unsigned long long ffma2(unsigned long long a,
                                                    unsigned long long b,
                                                    unsigned long long c) {
    unsigned long long d;
    asm("fma.rn.f32x2 %0, %1, %2, %3;" : "=l"(d) : "l"(a), "l"(b), "l"(c));
    return d;
}

// ---------------------------------------------------------------------------
// Kernel 1: per-(b,c) mean over N=256.  grid (128, 40), block 256 (8 warps)
__global__ void k_avg(const float* __restrict__ x) {
    int b = blockIdx.x;
    int c = blockIdx.y * 8 + (threadIdx.x >> 5);
    int lane = threadIdx.x & 31;
    const float* px = x + ((size_t)b * 320 + c) * 256;
    float s = 0.f;
#pragma unroll
    for (int i = 0; i < 8; i++) s += px[lane + 32 * i];
#pragma unroll
    for (int o = 16; o > 0; o >>= 1) s += __shfl_xor_sync(0xffffffffu, s, o);
    if (lane == 0) g_avg[b * 320 + c] = s * (1.0f / 256.0f);
}

// ---------------------------------------------------------------------------
// Kernel 2: channel attention MLP.  grid 128 (one per b), block 256.
__global__ void k_ca(const float* __restrict__ w1, const float* __restrict__ b1,
                     const float* __restrict__ w2, const float* __restrict__ b2) {
    __shared__ float av[320];
    __shared__ float hs[40];
    int b = blockIdx.x, tid = threadIdx.x;
    for (int e = tid; e < 320; e += 256) av[e] = g_avg[b * 320 + e];
    __syncthreads();
    if (tid < 40) {
        float s = b1[tid];
        for (int c = 0; c < 320; c++) s += av[c] * w1[tid * 320 + c];
        hs[tid] = fmaxf(s, 0.0f);
    }
    __syncthreads();
    for (int o = tid; o < 960; o += 256) {
        float s = b2[o];
#pragma unroll
        for (int k = 0; k < 40; k++) s += hs[k] * w2[o * 40 + k];
        g_cw[b * 960 + o] = 1.0f / (1.0f + expf(-s));
    }
}

// ---------------------------------------------------------------------------
// Kernel 3: build circular-conv kernels kappa[m] from the masks (JAX-exact fp32).
__device__ __forceinline__ float jsig(float z) { return 1.0f / (1.0f + expf(-z)); }

__global__ void k_prep(const float* __restrict__ lcp, const float* __restrict__ hcp) {
    __shared__ double ctab[16];
    int t = threadIdx.x;
    if (t < 16) ctab[t] = cos((double)t * 3.14159265358979323846 / 8.0);
    __syncthreads();
    float lc = *lcp, hc = *hcp;
    int a = t >> 4, bb = t & 15;
    float step = __fdiv_rn(2.0f, 15.0f);
    for (int m = 0; m < 2; m++) {
        double acc = 0.0;
        for (int u = 0; u < 16; u++) {
            int s = (u + 8) & 15;
            float yv = __fadd_rn(__fmul_rn((float)s, step), -1.0f);
            for (int v = 0; v < 16; v++) {
                int t2 = (v + 8) & 15;
                float xv = __fadd_rn(__fmul_rn((float)t2, step), -1.0f);
                float d2 = __fadd_rn(__fmul_rn(xv, xv), __fmul_rn(yv, yv));
                float d = __fdiv_rn(__fsqrt_rn(d2), 1.4142135623730951f);
                float mv;
                if (m == 0) {
                    mv = jsig(__fdiv_rn(__fsub_rn(lc, d), 1e-6f));
                } else {
                    float m1 = jsig(__fdiv_rn(__fsub_rn(d, lc), 1e-6f));
                    float m2 = jsig(__fdiv_rn(__fsub_rn(hc, d), 1e-6f));
                    mv = m1 * m2;
                }
                int ph = (u * a + v * bb) & 15;
                acc += (double)mv * ctab[ph];
            }
        }
        g_kappa[m][t] = (float)(acc * (1.0 / 256.0));
    }
}

// ---------------------------------------------------------------------------
// Kernel 4: band GEMM with FFMA2.  out[m][row][p] = sum_q x[row][q]*kappa[idx(p,q)]
__global__ __launch_bounds__(256) void k_band(const float* __restrict__ x) {
    __shared__ float As[64][32];
    __shared__ float Bs[32][256];
    __shared__ float ks[256];
    int m = blockIdx.y;
    int rows0 = blockIdx.x * 64;
    int tid = threadIdx.x;
    ks[tid] = g_kappa[m][tid];
    int tr = tid >> 5, tp = tid & 31;
    unsigned long long acc2[4][8];   // row-pairs (i=2pr, 2pr+1) x 8 cols
#pragma unroll
    for (int pr = 0; pr < 4; pr++)
#pragma unroll
        for (int j = 0; j < 8; j++) acc2[pr][j] = 0ull;
    int rl = tid >> 2, qo = (tid & 3) * 8;
    for (int kq = 0; kq < 256; kq += 32) {
        __syncthreads();
        const float4* src = (const float4*)(x + (size_t)(rows0 + rl) * 256 + kq + qo);
        float4 a0 = src[0], a1 = src[1];
        *((float4*)&As[rl][qo])     = a0;
        *((float4*)&As[rl][qo + 4]) = a1;
#pragma unroll
        for (int it = 0; it < 32; it++) {
            int q = kq + it, p = tid;
            int aa = ((p >> 4) - (q >> 4)) & 15;
            int bbq = ((p & 15) - (q & 15)) & 15;
            Bs[it][p] = ks[aa * 16 + bbq];
        }
        __syncthreads();
#pragma unroll
        for (int ql = 0; ql < 32; ql++) {
            unsigned long long av2[4], bv2[8];
#pragma unroll
            for (int pr = 0; pr < 4; pr++)
                av2[pr] = f2pack(As[tr * 8 + 2 * pr][ql], As[tr * 8 + 2 * pr + 1][ql]);
#pragma unroll
            for (int j = 0; j < 8; j++) {
                float bv = Bs[ql][tp + 32 * j];
                bv2[j] = f2pack(bv, bv);
            }
#pragma unroll
            for (int pr = 0; pr < 4; pr++)
#pragma unroll
                for (int j = 0; j < 8; j++)
                    acc2[pr][j] = ffma2(av2[pr], bv2[j], acc2[pr][j]);
        }
    }
    float* outp = g_bands[m];
#pragma unroll
    for (int pr = 0; pr < 4; pr++) {
        size_t r0 = (size_t)(rows0 + tr * 8 + 2 * pr) * 256;
        size_t r1 = r0 + 256;
#pragma unroll
        for (int j = 0; j < 8; j++) {
            float lo, hi;
            f2unpack(acc2[pr][j], lo, hi);
            outp[r0 + tp + 32 * j] = lo;
            outp[r1 + tp + 32 * j] = hi;
        }
    }
}

// ---------------------------------------------------------------------------
// Kernel 5: 3x3 conv + bias + GroupNorm + affine + residual, FFMA2 mainloop.
// grid (5 groups, 128 b, 3 bands), block 256.
// Block tile: 64 out-channels (== one GN group) x 256 pixels of one image.
// Thread tile: 8 co (as 4 packed pairs) x 8 px (half a pixel row).
__global__ __launch_bounds__(256, 2) void k_conv(
    const float* __restrict__ x,
    const float* __restrict__ wl, const float* __restrict__ bl,
    const float* __restrict__ gl, const float* __restrict__ el,
    const float* __restrict__ wm, const float* __restrict__ bm,
    const float* __restrict__ gm, const float* __restrict__ em,
    const float* __restrict__ wh, const float* __restrict__ bh,
    const float* __restrict__ gh, const float* __restrict__ eh) {
    __shared__ float in_s[8][18][19];   // padded 16x16 + halo, pitch 19 (bank-safe)
    __shared__ float w_s[8][9][64];     // [ci][tap][co]; co-pairs contiguous
    __shared__ float red_s[256];
    __shared__ float red_q[256];
    __shared__ float stats[2];

    int g = blockIdx.x, b = blockIdx.y, m = blockIdx.z;
    const float *W, *bias, *gam, *bet;
    if (m == 0)      { W = wl; bias = bl; gam = gl; bet = el; }
    else if (m == 1) { W = wm; bias = bm; gam = gm; bet = em; }
    else             { W = wh; bias = bh; gam = gh; bet = eh; }

    int tid = threadIdx.x;
    int tr = tid >> 5;          // co sub-tile: channels tr*8..tr*8+7 (warp-uniform)
    int tc = tid & 31;
    int r  = tc >> 1;           // pixel row 0..15
    int x0 = (tc & 1) * 8;      // pixel col base 0 or 8

    for (int e = tid; e < 8 * 18 * 19; e += 256) ((float*)in_s)[e] = 0.0f;

    unsigned long long acc2[4][8];   // co-pairs x 8 px
#pragma unroll
    for (int pr = 0; pr < 4; pr++)
#pragma unroll
        for (int px = 0; px < 8; px++) acc2[pr][px] = 0ull;

    const size_t base_in = (size_t)b * 81920;
    const float* band0 = g_bands[0];
    const float* band1 = g_bands[1];

    for (int cc = 0; cc < 40; cc++) {           // 40 chunks of 8 input channels
        __syncthreads();
#pragma unroll
        for (int it = 0; it < 8; it++) {        // load 8x256 inputs
            int cl = it, p = tid;
            size_t off = base_in + (size_t)(cc * 8 + cl) * 256 + p;
            float v;
            if (m == 0)      v = band0[off];
            else if (m == 1) v = band1[off];
            else             v = x[off] - band0[off] - band1[off];
            in_s[cl][1 + (p >> 4)][1 + (p & 15)] = v;
        }
#pragma unroll
        for (int it = 0; it < 18; it++) {       // load 64co x 8ci x 9 weights
            int e = tid + 256 * it;
            int co = e / 72, rem = e % 72;
            int cl = rem / 9, k = rem % 9;
            w_s[cl][k][co] = W[(size_t)(g * 64 + co) * 2880 + (cc * 8 + cl) * 9 + k];
        }
        __syncthreads();
#pragma unroll
        for (int cl = 0; cl < 8; cl++) {
#pragma unroll
            for (int ky = 0; ky < 3; ky++) {
                // one input row for this tap row; broadcast-pack each pixel
                unsigned long long rin2[10];
#pragma unroll
                for (int dx = 0; dx < 10; dx++) {
                    float rv = in_s[cl][r + ky][x0 + dx];
                    rin2[dx] = f2pack(rv, rv);
                }
#pragma unroll
                for (int kx = 0; kx < 3; kx++) {
                    // co-pairs straight out of shared as 64-bit values
                    const ulonglong2* wp =
                        (const ulonglong2*)&w_s[cl][ky * 3 + kx][tr * 8];
                    ulonglong2 wa = wp[0], wb = wp[1];
                    unsigned long long w2[4] = {wa.x, wa.y, wb.x, wb.y};
#pragma unroll
                    for (int pr = 0; pr < 4; pr++)
#pragma unroll
                        for (int px = 0; px < 8; px++)
                            acc2[pr][px] = ffma2(w2[pr], rin2[px + kx], acc2[pr][px]);
                }
            }
        }
    }
    // unpack accumulators, add bias (before GN stats, matching reference)
    float acc[8][8];
#pragma unroll
    for (int pr = 0; pr < 4; pr++)
#pragma unroll
        for (int px = 0; px < 8; px++)
            f2unpack(acc2[pr][px], acc[2 * pr][px], acc[2 * pr + 1][px]);
#pragma unroll
    for (int ci = 0; ci < 8; ci++) {
        float bv = bias[g * 64 + tr * 8 + ci];
#pragma unroll
        for (int px = 0; px < 8; px++) acc[ci][px] += bv;
    }
    // GroupNorm over exactly this block's 64ch x 256px
    float s = 0.f, q = 0.f;
#pragma unroll
    for (int ci = 0; ci < 8; ci++)
#pragma unroll
        for (int px = 0; px < 8; px++) { float v = acc[ci][px]; s += v; q += v * v; }
    red_s[tid] = s; red_q[tid] = q;
    __syncthreads();
    for (int off = 128; off > 0; off >>= 1) {
        if (tid < off) { red_s[tid] += red_s[tid + off]; red_q[tid] += red_q[tid + off]; }
        __syncthreads();
    }
    if (tid == 0) {
        float mu  = red_s[0] * (1.0f / 16384.0f);
        float var = red_q[0] * (1.0f / 16384.0f) - mu * mu;
        stats[0] = mu;
        stats[1] = rsqrtf(var + 1e-5f);
    }
    __syncthreads();
    float mu = stats[0], rs = stats[1];
    float* feat = g_feat[m];
#pragma unroll
    for (int ci = 0; ci < 8; ci++) {
        int c = g * 64 + tr * 8 + ci;
        float ga = gam[c], be = bet[c];
        size_t o = base_in + (size_t)c * 256 + r * 16 + x0;
#pragma unroll
        for (int px = 0; px < 8; px++)
            feat[o + px] = (acc[ci][px] - mu) * rs * ga + be + x[o + px];
    }
}

// ---------------------------------------------------------------------------
// Kernel 6: fused = sum_m cw_m*feat_m; sw = sigmoid(<fused, sa_w> + sa_b);
// out = fused * sw.  grid 128 (b), block 256 (one thread per pixel).
__global__ void k_fuse(const float* __restrict__ saw, const float* __restrict__ sab,
                       float* __restrict__ out) {
    __shared__ float cw_s[960];
    __shared__ float saw_s[320];
    int b = blockIdx.x, p = threadIdx.x;
    for (int e = p; e < 960; e += 256) cw_s[e] = g_cw[b * 960 + e];
    for (int e = p; e < 320; e += 256) saw_s[e] = saw[e];
    __syncthreads();
    size_t base = (size_t)b * 81920 + p;
    float sacc = 0.f;
    for (int c = 0; c < 320; c++) {
        size_t o = base + (size_t)c * 256;
        float f = cw_s[c] * g_feat[0][o] + cw_s[320 + c] * g_feat[1][o]
                + cw_s[640 + c] * g_feat[2][o];
        sacc += f * saw_s[c];
    }
    float sw = 1.0f / (1.0f + expf(-(sacc + sab[0])));
    for (int c = 0; c < 320; c++) {
        size_t o = base + (size_t)c * 256;
        float f = cw_s[c] * g_feat[0][o] + cw_s[320 + c] * g_feat[1][o]
                + cw_s[640 + c] * g_feat[2][o];
        out[o] = f * sw;
    }
}

// ---------------------------------------------------------------------------
extern "C" void kernel_launch(void* const* d_in, const int* in_sizes, int n_in,
                              void* d_out, int out_size) {
    const float* x   = (const float*)d_in[0];
    const float* lc  = (const float*)d_in[1];
    const float* hc  = (const float*)d_in[2];
    const float* w1  = (const float*)d_in[3];
    const float* b1  = (const float*)d_in[4];
    const float* w2  = (const float*)d_in[5];
    const float* b2  = (const float*)d_in[6];
    const float* wl  = (const float*)d_in[7];
    const float* bl  = (const float*)d_in[8];
    const float* gl  = (const float*)d_in[9];
    const float* el  = (const float*)d_in[10];
    const float* wm  = (const float*)d_in[11];
    const float* bm  = (const float*)d_in[12];
    const float* gm  = (const float*)d_in[13];
    const float* em  = (const float*)d_in[14];
    const float* wh  = (const float*)d_in[15];
    const float* bh  = (const float*)d_in[16];
    const float* gh  = (const float*)d_in[17];
    const float* eh  = (const float*)d_in[18];
    const float* saw = (const float*)d_in[19];
    const float* sab = (const float*)d_in[20];
    float* out = (float*)d_out;

    k_avg <<<dim3(128, 40), 256>>>(x);
    k_ca  <<<128, 256>>>(w1, b1, w2, b2);
    k_prep<<<1, 256>>>(lc, hc);
    k_band<<<dim3(640, 2), 256>>>(x);
    k_conv<<<dim3(5, 128, 3), 256>>>(x, wl, bl, gl, el, wm, bm, gm, em, wh, bh, gh, eh);
    k_fuse<<<128, 256>>>(saw, sab, out);
}

// round 6
// speedup vs baseline: 2.3507x; 2.3379x over previous
#include <cuda_runtime.h>
#include <cuda_fp16.h>
#include <math.h>
#include <stdint.h>

#define SZ 10485760
__device__ float g_bands[3][SZ];     // low, mid, high
__device__ float g_feat[3][SZ];
__device__ float g_avg[40960];
__device__ float g_cw[128 * 960];
__device__ float g_kappa[2][256];
__device__ __align__(16) __half g_Wh[2764800];  // [m][ci320][tap9][co320]

__device__ __forceinline__ uint32_t s2u(const void* p) {
    uint32_t a;
    asm("{ .reg .u64 t; cvta.to.shared.u64 t, %1; cvt.u32.u64 %0, t; }" : "=r"(a) : "l"(p));
    return a;
}

// ---------------------------------------------------------------------------
__global__ void k_avg(const float* __restrict__ x) {
    int b = blockIdx.x;
    int c = blockIdx.y * 8 + (threadIdx.x >> 5);
    int lane = threadIdx.x & 31;
    const float* px = x + ((size_t)b * 320 + c) * 256;
    float s = 0.f;
#pragma unroll
    for (int i = 0; i < 8; i++) s += px[lane + 32 * i];
#pragma unroll
    for (int o = 16; o > 0; o >>= 1) s += __shfl_xor_sync(0xffffffffu, s, o);
    if (lane == 0) g_avg[b * 320 + c] = s * (1.0f / 256.0f);
}

__global__ void k_ca(const float* __restrict__ w1, const float* __restrict__ b1,
                     const float* __restrict__ w2, const float* __restrict__ b2) {
    __shared__ float av[320];
    __shared__ float hs[40];
    int b = blockIdx.x, tid = threadIdx.x;
    for (int e = tid; e < 320; e += 256) av[e] = g_avg[b * 320 + e];
    __syncthreads();
    if (tid < 40) {
        float s = b1[tid];
        for (int c = 0; c < 320; c++) s += av[c] * w1[tid * 320 + c];
        hs[tid] = fmaxf(s, 0.0f);
    }
    __syncthreads();
    for (int o = tid; o < 960; o += 256) {
        float s = b2[o];
#pragma unroll
        for (int k = 0; k < 40; k++) s += hs[k] * w2[o * 40 + k];
        g_cw[b * 960 + o] = 1.0f / (1.0f + expf(-s));
    }
}

__device__ __forceinline__ float jsig(float z) { return 1.0f / (1.0f + expf(-z)); }

__global__ void k_prep(const float* __restrict__ lcp, const float* __restrict__ hcp) {
    __shared__ double ctab[16];
    int t = threadIdx.x;
    if (t < 16) ctab[t] = cos((double)t * 3.14159265358979323846 / 8.0);
    __syncthreads();
    float lc = *lcp, hc = *hcp;
    int a = t >> 4, bb = t & 15;
    float step = __fdiv_rn(2.0f, 15.0f);
    for (int m = 0; m < 2; m++) {
        double acc = 0.0;
        for (int u = 0; u < 16; u++) {
            int s = (u + 8) & 15;
            float yv = __fadd_rn(__fmul_rn((float)s, step), -1.0f);
            for (int v = 0; v < 16; v++) {
                int t2 = (v + 8) & 15;
                float xv = __fadd_rn(__fmul_rn((float)t2, step), -1.0f);
                float d2 = __fadd_rn(__fmul_rn(xv, xv), __fmul_rn(yv, yv));
                float d = __fdiv_rn(__fsqrt_rn(d2), 1.4142135623730951f);
                float mv;
                if (m == 0) {
                    mv = jsig(__fdiv_rn(__fsub_rn(lc, d), 1e-6f));
                } else {
                    float m1 = jsig(__fdiv_rn(__fsub_rn(d, lc), 1e-6f));
                    float m2 = jsig(__fdiv_rn(__fsub_rn(hc, d), 1e-6f));
                    mv = m1 * m2;
                }
                int ph = (u * a + v * bb) & 15;
                acc += (double)mv * ctab[ph];
            }
        }
        g_kappa[m][t] = (float)(acc * (1.0 / 256.0));
    }
}

// band GEMM (round-1 scalar form)
__global__ __launch_bounds__(256) void k_band(const float* __restrict__ x) {
    __shared__ float As[64][32];
    __shared__ float Bs[32][256];
    __shared__ float ks[256];
    int m = blockIdx.y;
    int rows0 = blockIdx.x * 64;
    int tid = threadIdx.x;
    ks[tid] = g_kappa[m][tid];
    int tr = tid >> 5, tp = tid & 31;
    float acc[8][8];
#pragma unroll
    for (int i = 0; i < 8; i++)
#pragma unroll
        for (int j = 0; j < 8; j++) acc[i][j] = 0.f;
    int rl = tid >> 2, qo = (tid & 3) * 8;
    for (int kq = 0; kq < 256; kq += 32) {
        __syncthreads();
        const float4* src = (const float4*)(x + (size_t)(rows0 + rl) * 256 + kq + qo);
        float4 a0 = src[0], a1 = src[1];
        *((float4*)&As[rl][qo]) = a0;
        *((float4*)&As[rl][qo + 4]) = a1;
#pragma unroll
        for (int it = 0; it < 32; it++) {
            int q = kq + it, p = tid;
            int aa = ((p >> 4) - (q >> 4)) & 15;
            int bbq = ((p & 15) - (q & 15)) & 15;
            Bs[it][p] = ks[aa * 16 + bbq];
        }
        __syncthreads();
#pragma unroll
        for (int ql = 0; ql < 32; ql++) {
            float av[8], bv[8];
#pragma unroll
            for (int i = 0; i < 8; i++) av[i] = As[tr * 8 + i][ql];
#pragma unroll
            for (int j = 0; j < 8; j++) bv[j] = Bs[ql][tp + 32 * j];
#pragma unroll
            for (int i = 0; i < 8; i++)
#pragma unroll
                for (int j = 0; j < 8; j++) acc[i][j] = fmaf(av[i], bv[j], acc[i][j]);
        }
    }
    float* outp = g_bands[m];
#pragma unroll
    for (int i = 0; i < 8; i++) {
        size_t ro = (size_t)(rows0 + tr * 8 + i) * 256;
#pragma unroll
        for (int j = 0; j < 8; j++) outp[ro + tp + 32 * j] = acc[i][j];
    }
}

// high band = x - low - mid (so conv reads one array per m)
__global__ void k_high(const float* __restrict__ x) {
    size_t i = (size_t)blockIdx.x * 256 + threadIdx.x;
    float4 xv = ((const float4*)x)[i];
    float4 b0 = ((const float4*)g_bands[0])[i];
    float4 b1 = ((const float4*)g_bands[1])[i];
    float4 r;
    r.x = xv.x - b0.x - b1.x; r.y = xv.y - b0.y - b1.y;
    r.z = xv.z - b0.z - b1.z; r.w = xv.w - b0.w - b1.w;
    ((float4*)g_bands[2])[i] = r;
}

// weight prep: f32 -> f16 in layout [m][ci][tap][co]
__global__ void k_wprep(const float* __restrict__ wl, const float* __restrict__ wm,
                        const float* __restrict__ wh) {
    int e = blockIdx.x;            // e = m*2880 + ci*9 + tap
    int citap = e % 2880, m = e / 2880;
    int co = threadIdx.x;
    const float* W = (m == 0) ? wl : ((m == 1) ? wm : wh);
    float w = W[(size_t)co * 2880 + citap];
    g_Wh[(size_t)e * 320 + co] = __float2half_rn(w);
}

// ---------------------------------------------------------------------------
// mma.sync conv + bias + GroupNorm + affine + residual.
// grid (5 cotile, 128 b, 3 m), block 256 (8 warps).
// Block tile: 256 px x 64 co (= one GN group). Warp: 64 px x 32 co.
// X smem: [324 padded px rows][16 ci] f16, 48B pitch, hi & lo copies.
// W smem: [9 tap][64 co][16 ci] f16, 32B rows.
#define XHOFF 0
#define XLOFF 15552
#define WSOFF 31104
#define REDOF 49536
#define STAOF 51584
#define DYNSM 51648

__global__ void __launch_bounds__(256, 2) k_conv(
    const float* __restrict__ x,
    const float* __restrict__ bl, const float* __restrict__ gl, const float* __restrict__ el,
    const float* __restrict__ bm, const float* __restrict__ gm, const float* __restrict__ em,
    const float* __restrict__ bh, const float* __restrict__ gh, const float* __restrict__ eh) {
    extern __shared__ char P[];
    uint32_t Pu = s2u(P);
    int tid = threadIdx.x;
    int cotile = blockIdx.x, b = blockIdx.y, m = blockIdx.z;
    const float* biasp = (m == 0) ? bl : ((m == 1) ? bm : bh);
    const float* gamp  = (m == 0) ? gl : ((m == 1) ? gm : gh);
    const float* betp  = (m == 0) ? el : ((m == 1) ? em : eh);
    const float* src = g_bands[m];

    // zero X hi+lo regions once (border rows stay zero = zero padding)
    for (int i = tid * 16; i < 31104; i += 4096)
        *(uint4*)(P + i) = make_uint4(0, 0, 0, 0);

    int lane = tid & 31, wid = tid >> 5;
    int wq = wid & 3, chh = wid >> 2;      // px quarter, co half
    uint32_t laneA[4];
#pragma unroll
    for (int mf = 0; mf < 4; mf++)
        laneA[mf] = Pu + XHOFF +
            (uint32_t)(((wq * 4 + mf) * 18 + (lane & 15)) * 48) + ((lane >> 4) * 16);

    float acc[4][4][4];
#pragma unroll
    for (int a = 0; a < 4; a++)
#pragma unroll
        for (int n = 0; n < 4; n++)
#pragma unroll
            for (int r = 0; r < 4; r++) acc[a][n][r] = 0.f;

    const size_t bimg = (size_t)b * 81920;

    for (int c = 0; c < 20; c++) {
        __syncthreads();
        {   // X tile: thread = pixel; 16 ci values -> hi/lo f16 rows
            int px = tid, r = px >> 4, cc = px & 15;
            uint32_t rowb = (uint32_t)(((r + 1) * 18 + (cc + 1)) * 48);
            const float* sp = src + bimg + (size_t)c * 16 * 256 + px;
            uint32_t hv[8], lv[8];
#pragma unroll
            for (int j = 0; j < 8; j++) {
                float v0 = sp[(size_t)(2 * j) * 256];
                float v1 = sp[(size_t)(2 * j + 1) * 256];
                __half h0 = __float2half_rn(v0), h1 = __float2half_rn(v1);
                __half l0 = __float2half_rn(v0 - __half2float(h0));
                __half l1 = __float2half_rn(v1 - __half2float(h1));
                hv[j] = (uint32_t)__half_as_ushort(h0) | ((uint32_t)__half_as_ushort(h1) << 16);
                lv[j] = (uint32_t)__half_as_ushort(l0) | ((uint32_t)__half_as_ushort(l1) << 16);
            }
            *(uint4*)(P + XHOFF + rowb)      = make_uint4(hv[0], hv[1], hv[2], hv[3]);
            *(uint4*)(P + XHOFF + rowb + 16) = make_uint4(hv[4], hv[5], hv[6], hv[7]);
            *(uint4*)(P + XLOFF + rowb)      = make_uint4(lv[0], lv[1], lv[2], lv[3]);
            *(uint4*)(P + XLOFF + rowb + 16) = make_uint4(lv[4], lv[5], lv[6], lv[7]);
        }
        // W tile: [tap][co64][k16]
        for (int i = tid; i < 9216; i += 256) {
            int co = i & 63, tap = (i >> 6) % 9, k = i / 576;
            __half w = g_Wh[(size_t)(m * 2880 + (c * 16 + k) * 9 + tap) * 320 +
                            cotile * 64 + co];
            *(__half*)(P + WSOFF + (tap * 64 + co) * 32 + k * 2) = w;
        }
        __syncthreads();

#pragma unroll
        for (int tap = 0; tap < 9; tap++) {
            uint32_t aoff = (uint32_t)(((tap / 3) * 18 + (tap % 3)) * 48);
            uint32_t bf[4][2];
#pragma unroll
            for (int nf = 0; nf < 4; nf++) {
                const char* wp = P + WSOFF +
                    ((tap * 64 + chh * 32 + nf * 8 + (lane >> 2)) * 32) + (lane & 3) * 4;
                bf[nf][0] = *(const uint32_t*)wp;
                bf[nf][1] = *(const uint32_t*)(wp + 16);
            }
#pragma unroll
            for (int pass = 0; pass < 2; pass++) {
                uint32_t po = pass ? (uint32_t)XLOFF : 0u;
#pragma unroll
                for (int mf = 0; mf < 4; mf++) {
                    uint32_t a0, a1, a2, a3;
                    asm volatile(
                        "ldmatrix.sync.aligned.m8n8.x4.shared.b16 {%0,%1,%2,%3}, [%4];"
                        : "=r"(a0), "=r"(a1), "=r"(a2), "=r"(a3)
                        : "r"(laneA[mf] + aoff + po));
#pragma unroll
                    for (int nf = 0; nf < 4; nf++)
                        asm volatile(
                            "mma.sync.aligned.m16n8k16.row.col.f32.f16.f16.f32 "
                            "{%0,%1,%2,%3}, {%4,%5,%6,%7}, {%8,%9}, {%0,%1,%2,%3};"
                            : "+f"(acc[mf][nf][0]), "+f"(acc[mf][nf][1]),
                              "+f"(acc[mf][nf][2]), "+f"(acc[mf][nf][3])
                            : "r"(a0), "r"(a1), "r"(a2), "r"(a3),
                              "r"(bf[nf][0]), "r"(bf[nf][1]));
                }
            }
        }
    }

    // ---- epilogue: bias + GN(64co x 256px) + affine + residual ----
    int co_base = cotile * 64 + chh * 32;
    float bias2[4][2];
#pragma unroll
    for (int nf = 0; nf < 4; nf++) {
        int co0 = co_base + nf * 8 + 2 * (lane & 3);
        bias2[nf][0] = biasp[co0];
        bias2[nf][1] = biasp[co0 + 1];
    }
    float s = 0.f, q = 0.f;
#pragma unroll
    for (int mf = 0; mf < 4; mf++)
#pragma unroll
        for (int nf = 0; nf < 4; nf++)
#pragma unroll
            for (int r = 0; r < 4; r++) {
                float v = acc[mf][nf][r] + bias2[nf][r & 1];
                s += v; q += v * v;
            }
    float* red_s = (float*)(P + REDOF);
    float* red_q = red_s + 256;
    red_s[tid] = s; red_q[tid] = q;
    __syncthreads();
    for (int off = 128; off > 0; off >>= 1) {
        if (tid < off) { red_s[tid] += red_s[tid + off]; red_q[tid] += red_q[tid + off]; }
        __syncthreads();
    }
    float* stat = (float*)(P + STAOF);
    if (tid == 0) {
        float mu = red_s[0] * (1.f / 16384.f);
        float var = red_q[0] * (1.f / 16384.f) - mu * mu;
        stat[0] = mu;
        stat[1] = rsqrtf(var + 1e-5f);
    }
    __syncthreads();
    float mu = stat[0], rs = stat[1];
    float* feat = g_feat[m];
#pragma unroll
    for (int nf = 0; nf < 4; nf++) {
        int co0 = co_base + nf * 8 + 2 * (lane & 3);
        float ga0 = gamp[co0], be0 = betp[co0];
        float ga1 = gamp[co0 + 1], be1 = betp[co0 + 1];
#pragma unroll
        for (int mf = 0; mf < 4; mf++) {
            int px0 = wq * 64 + mf * 16 + (lane >> 2);
#pragma unroll
            for (int r = 0; r < 4; r++) {
                int px = px0 + ((r >= 2) ? 8 : 0);
                int co = co0 + (r & 1);
                float v = acc[mf][nf][r] + bias2[nf][r & 1];
                float ga = (r & 1) ? ga1 : ga0;
                float be = (r & 1) ? be1 : be0;
                size_t o = bimg + (size_t)co * 256 + px;
                feat[o] = (v - mu) * rs * ga + be + x[o];
            }
        }
    }
}

// ---------------------------------------------------------------------------
__global__ void k_fuse(const float* __restrict__ saw, const float* __restrict__ sab,
                       float* __restrict__ out) {
    __shared__ float cw_s[960];
    __shared__ float saw_s[320];
    int b = blockIdx.x, p = threadIdx.x;
    for (int e = p; e < 960; e += 256) cw_s[e] = g_cw[b * 960 + e];
    for (int e = p; e < 320; e += 256) saw_s[e] = saw[e];
    __syncthreads();
    size_t base = (size_t)b * 81920 + p;
    float sacc = 0.f;
    for (int c = 0; c < 320; c++) {
        size_t o = base + (size_t)c * 256;
        float f = cw_s[c] * g_feat[0][o] + cw_s[320 + c] * g_feat[1][o]
                + cw_s[640 + c] * g_feat[2][o];
        sacc += f * saw_s[c];
    }
    float sw = 1.0f / (1.0f + expf(-(sacc + sab[0])));
    for (int c = 0; c < 320; c++) {
        size_t o = base + (size_t)c * 256;
        float f = cw_s[c] * g_feat[0][o] + cw_s[320 + c] * g_feat[1][o]
                + cw_s[640 + c] * g_feat[2][o];
        out[o] = f * sw;
    }
}

// ---------------------------------------------------------------------------
extern "C" void kernel_launch(void* const* d_in, const int* in_sizes, int n_in,
                              void* d_out, int out_size) {
    const float* x   = (const float*)d_in[0];
    const float* lc  = (const float*)d_in[1];
    const float* hc  = (const float*)d_in[2];
    const float* w1  = (const float*)d_in[3];
    const float* b1  = (const float*)d_in[4];
    const float* w2  = (const float*)d_in[5];
    const float* b2  = (const float*)d_in[6];
    const float* wl  = (const float*)d_in[7];
    const float* bl  = (const float*)d_in[8];
    const float* gl  = (const float*)d_in[9];
    const float* el  = (const float*)d_in[10];
    const float* wm  = (const float*)d_in[11];
    const float* bm  = (const float*)d_in[12];
    const float* gm  = (const float*)d_in[13];
    const float* em  = (const float*)d_in[14];
    const float* wh  = (const float*)d_in[15];
    const float* bh  = (const float*)d_in[16];
    const float* gh  = (const float*)d_in[17];
    const float* eh  = (const float*)d_in[18];
    const float* saw = (const float*)d_in[19];
    const float* sab = (const float*)d_in[20];
    float* out = (float*)d_out;

    static int smset = 0;
    if (!smset) {
        cudaFuncSetAttribute(k_conv, cudaFuncAttributeMaxDynamicSharedMemorySize, DYNSM);
        smset = 1;
    }

    k_wprep<<<3 * 2880, 320>>>(wl, wm, wh);
    k_avg  <<<dim3(128, 40), 256>>>(x);
    k_ca   <<<128, 256>>>(w1, b1, w2, b2);
    k_prep <<<1, 256>>>(lc, hc);
    k_band <<<dim3(640, 2), 256>>>(x);
    k_high <<<10240, 256>>>(x);
    k_conv <<<dim3(5, 128, 3), 256, DYNSM>>>(x, bl, gl, el, bm, gm, em, bh, gh, eh);
    k_fuse <<<128, 256>>>(saw, sab, out);
}

// round 8
// speedup vs baseline: 3.2732x; 1.3924x over previous
#include <cuda_runtime.h>
#include <cuda_fp16.h>
#include <math.h>
#include <stdint.h>

#define SZ 10485760
__device__ float g_bands[3][SZ];     // low, mid, high
__device__ float g_feat[3][SZ];
__device__ float g_avg[40960];
__device__ float g_cw[128 * 960];
__device__ float g_kappa[2][256];
__device__ __align__(16) __half g_Wh[2764800];  // [m][ci320][tap9][co320]

__device__ __forceinline__ uint32_t s2u(const void* p) {
    uint32_t a;
    asm("{ .reg .u64 t; cvta.to.shared.u64 t, %1; cvt.u32.u64 %0, t; }" : "=r"(a) : "l"(p));
    return a;
}

// ---------------------------------------------------------------------------
__global__ void k_avg(const float* __restrict__ x) {
    int b = blockIdx.x;
    int c = blockIdx.y * 8 + (threadIdx.x >> 5);
    int lane = threadIdx.x & 31;
    const float* px = x + ((size_t)b * 320 + c) * 256;
    float s = 0.f;
#pragma unroll
    for (int i = 0; i < 8; i++) s += px[lane + 32 * i];
#pragma unroll
    for (int o = 16; o > 0; o >>= 1) s += __shfl_xor_sync(0xffffffffu, s, o);
    if (lane == 0) g_avg[b * 320 + c] = s * (1.0f / 256.0f);
}

__global__ void k_ca(const float* __restrict__ w1, const float* __restrict__ b1,
                     const float* __restrict__ w2, const float* __restrict__ b2) {
    __shared__ float av[320];
    __shared__ float hs[40];
    int b = blockIdx.x, tid = threadIdx.x;
    for (int e = tid; e < 320; e += 256) av[e] = g_avg[b * 320 + e];
    __syncthreads();
    if (tid < 40) {
        float s = b1[tid];
        for (int c = 0; c < 320; c++) s += av[c] * w1[tid * 320 + c];
        hs[tid] = fmaxf(s, 0.0f);
    }
    __syncthreads();
    for (int o = tid; o < 960; o += 256) {
        float s = b2[o];
#pragma unroll
        for (int k = 0; k < 40; k++) s += hs[k] * w2[o * 40 + k];
        g_cw[b * 960 + o] = 1.0f / (1.0f + expf(-s));
    }
}

__device__ __forceinline__ float jsig(float z) { return 1.0f / (1.0f + expf(-z)); }

// kappa: one block per (m, output); thread = one (u,v) term; double tree-reduce.
__global__ void k_prep(const float* __restrict__ lcp, const float* __restrict__ hcp) {
    __shared__ double ctab[16];
    __shared__ double red[256];
    int tid = threadIdx.x;
    if (tid < 16) ctab[tid] = cos((double)tid * 3.14159265358979323846 / 8.0);
    __syncthreads();
    float lc = *lcp, hc = *hcp;
    int bx = blockIdx.x;
    int m = bx >> 8, t = bx & 255;
    int a = t >> 4, bb = t & 15;
    int u = tid >> 4, v = tid & 15;
    float step = __fdiv_rn(2.0f, 15.0f);
    int s = (u + 8) & 15, t2 = (v + 8) & 15;
    float yv = __fadd_rn(__fmul_rn((float)s, step), -1.0f);
    float xv = __fadd_rn(__fmul_rn((float)t2, step), -1.0f);
    float d2 = __fadd_rn(__fmul_rn(xv, xv), __fmul_rn(yv, yv));
    float d = __fdiv_rn(__fsqrt_rn(d2), 1.4142135623730951f);
    float mv;
    if (m == 0) {
        mv = jsig(__fdiv_rn(__fsub_rn(lc, d), 1e-6f));
    } else {
        float m1 = jsig(__fdiv_rn(__fsub_rn(d, lc), 1e-6f));
        float m2 = jsig(__fdiv_rn(__fsub_rn(hc, d), 1e-6f));
        mv = m1 * m2;
    }
    int ph = (u * a + v * bb) & 15;
    red[tid] = (double)mv * ctab[ph];
    __syncthreads();
    for (int off = 128; off > 0; off >>= 1) {
        if (tid < off) red[tid] += red[tid + off];
        __syncthreads();
    }
    if (tid == 0) g_kappa[m][t] = (float)(red[0] * (1.0 / 256.0));
}

// band GEMM (scalar)
__global__ __launch_bounds__(256) void k_band(const float* __restrict__ x) {
    __shared__ float As[64][32];
    __shared__ float Bs[32][256];
    __shared__ float ks[256];
    int m = blockIdx.y;
    int rows0 = blockIdx.x * 64;
    int tid = threadIdx.x;
    ks[tid] = g_kappa[m][tid];
    int tr = tid >> 5, tp = tid & 31;
    float acc[8][8];
#pragma unroll
    for (int i = 0; i < 8; i++)
#pragma unroll
        for (int j = 0; j < 8; j++) acc[i][j] = 0.f;
    int rl = tid >> 2, qo = (tid & 3) * 8;
    for (int kq = 0; kq < 256; kq += 32) {
        __syncthreads();
        const float4* src = (const float4*)(x + (size_t)(rows0 + rl) * 256 + kq + qo);
        float4 a0 = src[0], a1 = src[1];
        *((float4*)&As[rl][qo]) = a0;
        *((float4*)&As[rl][qo + 4]) = a1;
#pragma unroll
        for (int it = 0; it < 32; it++) {
            int q = kq + it, p = tid;
            int aa = ((p >> 4) - (q >> 4)) & 15;
            int bbq = ((p & 15) - (q & 15)) & 15;
            Bs[it][p] = ks[aa * 16 + bbq];
        }
        __syncthreads();
#pragma unroll
        for (int ql = 0; ql < 32; ql++) {
            float av[8], bv[8];
#pragma unroll
            for (int i = 0; i < 8; i++) av[i] = As[tr * 8 + i][ql];
#pragma unroll
            for (int j = 0; j < 8; j++) bv[j] = Bs[ql][tp + 32 * j];
#pragma unroll
            for (int i = 0; i < 8; i++)
#pragma unroll
                for (int j = 0; j < 8; j++) acc[i][j] = fmaf(av[i], bv[j], acc[i][j]);
        }
    }
    float* outp = g_bands[m];
#pragma unroll
    for (int i = 0; i < 8; i++) {
        size_t ro = (size_t)(rows0 + tr * 8 + i) * 256;
#pragma unroll
        for (int j = 0; j < 8; j++) outp[ro + tp + 32 * j] = acc[i][j];
    }
}

__global__ void k_high(const float* __restrict__ x) {
    size_t i = (size_t)blockIdx.x * 256 + threadIdx.x;
    float4 xv = ((const float4*)x)[i];
    float4 b0 = ((const float4*)g_bands[0])[i];
    float4 b1 = ((const float4*)g_bands[1])[i];
    float4 r;
    r.x = xv.x - b0.x - b1.x; r.y = xv.y - b0.y - b1.y;
    r.z = xv.z - b0.z - b1.z; r.w = xv.w - b0.w - b1.w;
    ((float4*)g_bands[2])[i] = r;
}

// weight prep: f32 -> f16 [m][ci][tap][co], float4 loads + coalesced stores
__global__ void k_wprep(const float* __restrict__ wl, const float* __restrict__ wm,
                        const float* __restrict__ wh) {
    int e = blockIdx.x;            // 3*720
    int m = e / 720, ct4 = (e % 720) * 4;
    int co = threadIdx.x;
    const float* W = (m == 0) ? wl : ((m == 1) ? wm : wh);
    float4 wv = *(const float4*)(W + (size_t)co * 2880 + ct4);
    size_t o = (size_t)(m * 2880 + ct4) * 320 + co;
    g_Wh[o]       = __float2half_rn(wv.x);
    g_Wh[o + 320] = __float2half_rn(wv.y);
    g_Wh[o + 640] = __float2half_rn(wv.z);
    g_Wh[o + 960] = __float2half_rn(wv.w);
}

// ---------------------------------------------------------------------------
// single-pass f16 mma.sync conv + bias + GroupNorm + affine + residual.
// grid (5 cotile, 128 b, 3 m), block 256 (8 warps).
#define XHOFF 0
#define WSOFF 15552
#define REDOF 33984
#define STAOF 36032
#define DYNSM 36096

__global__ void __launch_bounds__(256, 2) k_conv(
    const float* __restrict__ x,
    const float* __restrict__ bl, const float* __restrict__ gl, const float* __restrict__ el,
    const float* __restrict__ bm, const float* __restrict__ gm, const float* __restrict__ em,
    const float* __restrict__ bh, const float* __restrict__ gh, const float* __restrict__ eh) {
    extern __shared__ char P[];
    uint32_t Pu = s2u(P);
    int tid = threadIdx.x;
    int cotile = blockIdx.x, b = blockIdx.y, m = blockIdx.z;
    const float* biasp = (m == 0) ? bl : ((m == 1) ? bm : bh);
    const float* gamp  = (m == 0) ? gl : ((m == 1) ? gm : gh);
    const float* betp  = (m == 0) ? el : ((m == 1) ? em : eh);
    const float* src = g_bands[m];

    for (int i = tid * 16; i < 15552; i += 4096)
        *(uint4*)(P + i) = make_uint4(0, 0, 0, 0);

    int lane = tid & 31, wid = tid >> 5;
    int wq = wid & 3, chh = wid >> 2;
    uint32_t laneA[4];
#pragma unroll
    for (int mf = 0; mf < 4; mf++)
        laneA[mf] = Pu + XHOFF +
            (uint32_t)(((wq * 4 + mf) * 18 + (lane & 15)) * 48) + ((lane >> 4) * 16);

    float acc[4][4][4];
#pragma unroll
    for (int a = 0; a < 4; a++)
#pragma unroll
        for (int n = 0; n < 4; n++)
#pragma unroll
            for (int r = 0; r < 4; r++) acc[a][n][r] = 0.f;

    const size_t bimg = (size_t)b * 81920;

    for (int c = 0; c < 20; c++) {
        __syncthreads();
        {   // X tile: thread = pixel; 16 ci values f16
            int px = tid, r = px >> 4, cc = px & 15;
            uint32_t rowb = (uint32_t)(((r + 1) * 18 + (cc + 1)) * 48);
            const float* sp = src + bimg + (size_t)c * 16 * 256 + px;
            uint32_t hv[8];
#pragma unroll
            for (int j = 0; j < 8; j++) {
                float v0 = sp[(size_t)(2 * j) * 256];
                float v1 = sp[(size_t)(2 * j + 1) * 256];
                hv[j] = (uint32_t)__half_as_ushort(__float2half_rn(v0)) |
                        ((uint32_t)__half_as_ushort(__float2half_rn(v1)) << 16);
            }
            *(uint4*)(P + XHOFF + rowb)      = make_uint4(hv[0], hv[1], hv[2], hv[3]);
            *(uint4*)(P + XHOFF + rowb + 16) = make_uint4(hv[4], hv[5], hv[6], hv[7]);
        }
        for (int i = tid; i < 9216; i += 256) {
            int co = i & 63, tap = (i >> 6) % 9, k = i / 576;
            __half w = g_Wh[(size_t)(m * 2880 + (c * 16 + k) * 9 + tap) * 320 +
                            cotile * 64 + co];
            *(__half*)(P + WSOFF + (tap * 64 + co) * 32 + k * 2) = w;
        }
        __syncthreads();

#pragma unroll
        for (int tap = 0; tap < 9; tap++) {
            uint32_t aoff = (uint32_t)(((tap / 3) * 18 + (tap % 3)) * 48);
            uint32_t bf[4][2];
#pragma unroll
            for (int nf = 0; nf < 4; nf++) {
                const char* wp = P + WSOFF +
                    ((tap * 64 + chh * 32 + nf * 8 + (lane >> 2)) * 32) + (lane & 3) * 4;
                bf[nf][0] = *(const uint32_t*)wp;
                bf[nf][1] = *(const uint32_t*)(wp + 16);
            }
#pragma unroll
            for (int mf = 0; mf < 4; mf++) {
                uint32_t a0, a1, a2, a3;
                asm volatile(
                    "ldmatrix.sync.aligned.m8n8.x4.shared.b16 {%0,%1,%2,%3}, [%4];"
                    : "=r"(a0), "=r"(a1), "=r"(a2), "=r"(a3)
                    : "r"(laneA[mf] + aoff));
#pragma unroll
                for (int nf = 0; nf < 4; nf++)
                    asm volatile(
                        "mma.sync.aligned.m16n8k16.row.col.f32.f16.f16.f32 "
                        "{%0,%1,%2,%3}, {%4,%5,%6,%7}, {%8,%9}, {%0,%1,%2,%3};"
                        : "+f"(acc[mf][nf][0]), "+f"(acc[mf][nf][1]),
                          "+f"(acc[mf][nf][2]), "+f"(acc[mf][nf][3])
                        : "r"(a0), "r"(a1), "r"(a2), "r"(a3),
                          "r"(bf[nf][0]), "r"(bf[nf][1]));
            }
        }
    }

    // ---- epilogue ----
    int co_base = cotile * 64 + chh * 32;
    float bias2[4][2];
#pragma unroll
    for (int nf = 0; nf < 4; nf++) {
        int co0 = co_base + nf * 8 + 2 * (lane & 3);
        bias2[nf][0] = biasp[co0];
        bias2[nf][1] = biasp[co0 + 1];
    }
    float s = 0.f, q = 0.f;
#pragma unroll
    for (int mf = 0; mf < 4; mf++)
#pragma unroll
        for (int nf = 0; nf < 4; nf++)
#pragma unroll
            for (int r = 0; r < 4; r++) {
                float v = acc[mf][nf][r] + bias2[nf][r & 1];
                s += v; q += v * v;
            }
    float* red_s = (float*)(P + REDOF);
    float* red_q = red_s + 256;
    red_s[tid] = s; red_q[tid] = q;
    __syncthreads();
    for (int off = 128; off > 0; off >>= 1) {
        if (tid < off) { red_s[tid] += red_s[tid + off]; red_q[tid] += red_q[tid + off]; }
        __syncthreads();
    }
    float* stat = (float*)(P + STAOF);
    if (tid == 0) {
        float mu = red_s[0] * (1.f / 16384.f);
        float var = red_q[0] * (1.f / 16384.f) - mu * mu;
        stat[0] = mu;
        stat[1] = rsqrtf(var + 1e-5f);
    }
    __syncthreads();
    float mu = stat[0], rs = stat[1];
    float* feat = g_feat[m];
#pragma unroll
    for (int nf = 0; nf < 4; nf++) {
        int co0 = co_base + nf * 8 + 2 * (lane & 3);
        float ga0 = gamp[co0], be0 = betp[co0];
        float ga1 = gamp[co0 + 1], be1 = betp[co0 + 1];
#pragma unroll
        for (int mf = 0; mf < 4; mf++) {
            int px0 = wq * 64 + mf * 16 + (lane >> 2);
#pragma unroll
            for (int r = 0; r < 4; r++) {
                int px = px0 + ((r >= 2) ? 8 : 0);
                int co = co0 + (r & 1);
                float v = acc[mf][nf][r] + bias2[nf][r & 1];
                float ga = (r & 1) ? ga1 : ga0;
                float be = (r & 1) ? be1 : be0;
                size_t o = bimg + (size_t)co * 256 + px;
                feat[o] = (v - mu) * rs * ga + be + x[o];
            }
        }
    }
}

// ---------------------------------------------------------------------------
__global__ void k_fuse(const float* __restrict__ saw, const float* __restrict__ sab,
                       float* __restrict__ out) {
    __shared__ float cw_s[960];
    __shared__ float saw_s[320];
    int b = blockIdx.x, p = threadIdx.x;
    for (int e = p; e < 960; e += 256) cw_s[e] = g_cw[b * 960 + e];
    for (int e = p; e < 320; e += 256) saw_s[e] = saw[e];
    __syncthreads();
    size_t base = (size_t)b * 81920 + p;
    float sacc = 0.f;
    for (int c = 0; c < 320; c++) {
        size_t o = base + (size_t)c * 256;
        float f = cw_s[c] * g_feat[0][o] + cw_s[320 + c] * g_feat[1][o]
                + cw_s[640 + c] * g_feat[2][o];
        sacc += f * saw_s[c];
    }
    float sw = 1.0f / (1.0f + expf(-(sacc + sab[0])));
    for (int c = 0; c < 320; c++) {
        size_t o = base + (size_t)c * 256;
        float f = cw_s[c] * g_feat[0][o] + cw_s[320 + c] * g_feat[1][o]
                + cw_s[640 + c] * g_feat[2][o];
        out[o] = f * sw;
    }
}

// ---------------------------------------------------------------------------
extern "C" void kernel_launch(void* const* d_in, const int* in_sizes, int n_in,
                              void* d_out, int out_size) {
    const float* x   = (const float*)d_in[0];
    const float* lc  = (const float*)d_in[1];
    const float* hc  = (const float*)d_in[2];
    const float* w1  = (const float*)d_in[3];
    const float* b1  = (const float*)d_in[4];
    const float* w2  = (const float*)d_in[5];
    const float* b2  = (const float*)d_in[6];
    const float* wl  = (const float*)d_in[7];
    const float* bl  = (const float*)d_in[8];
    const float* gl  = (const float*)d_in[9];
    const float* el  = (const float*)d_in[10];
    const float* wm  = (const float*)d_in[11];
    const float* bm  = (const float*)d_in[12];
    const float* gm  = (const float*)d_in[13];
    const float* em  = (const float*)d_in[14];
    const float* wh  = (const float*)d_in[15];
    const float* bh  = (const float*)d_in[16];
    const float* gh  = (const float*)d_in[17];
    const float* eh  = (const float*)d_in[18];
    const float* saw = (const float*)d_in[19];
    const float* sab = (const float*)d_in[20];
    float* out = (float*)d_out;

    static int smset = 0;
    if (!smset) {
        cudaFuncSetAttribute(k_conv, cudaFuncAttributeMaxDynamicSharedMemorySize, DYNSM);
        smset = 1;
    }

    k_wprep<<<2160, 320>>>(wl, wm, wh);
    k_avg  <<<dim3(128, 40), 256>>>(x);
    k_ca   <<<128, 256>>>(w1, b1, w2, b2);
    k_prep <<<512, 256>>>(lc, hc);
    k_band <<<dim3(640, 2), 256>>>(x);
    k_high <<<10240, 256>>>(x);
    k_conv <<<dim3(5, 128, 3), 256, DYNSM>>>(x, bl, gl, el, bm, gm, em, bh, gh, eh);
    k_fuse <<<128, 256>>>(saw, sab, out);
}

// round 13
// speedup vs baseline: 4.9390x; 1.5090x over previous
#include <cuda_runtime.h>
#include <cuda_fp16.h>
#include <math.h>
#include <stdint.h>

#define SZ 10485760
__device__ float g_bands[3][SZ];     // low, mid, high
__device__ float g_feat[3][SZ];
__device__ float g_avg[40960];
__device__ float g_cw[128 * 960];
__device__ float g_kappa[2][256];
__device__ __align__(16) __half g_Wh[2764800];   // [m][cotile][chunk][tap][k16][co64]

__device__ __forceinline__ uint32_t s2u(const void* p) {
    uint32_t a;
    asm("{ .reg .u64 t; cvta.to.shared.u64 t, %1; cvt.u32.u64 %0, t; }" : "=r"(a) : "l"(p));
    return a;
}

// ---------------------------------------------------------------------------
__global__ void k_avg(const float* __restrict__ x) {
    int b = blockIdx.x;
    int c = blockIdx.y * 8 + (threadIdx.x >> 5);
    int lane = threadIdx.x & 31;
    const float* px = x + ((size_t)b * 320 + c) * 256;
    float s = 0.f;
#pragma unroll
    for (int i = 0; i < 8; i++) s += px[lane + 32 * i];
#pragma unroll
    for (int o = 16; o > 0; o >>= 1) s += __shfl_xor_sync(0xffffffffu, s, o);
    if (lane == 0) g_avg[b * 320 + c] = s * (1.0f / 256.0f);
}

__global__ void k_ca(const float* __restrict__ w1, const float* __restrict__ b1,
                     const float* __restrict__ w2, const float* __restrict__ b2) {
    __shared__ float av[320];
    __shared__ float hs[40];
    int b = blockIdx.x, tid = threadIdx.x;
    for (int e = tid; e < 320; e += 256) av[e] = g_avg[b * 320 + e];
    __syncthreads();
    if (tid < 40) {
        float s = b1[tid];
        for (int c = 0; c < 320; c++) s += av[c] * w1[tid * 320 + c];
        hs[tid] = fmaxf(s, 0.0f);
    }
    __syncthreads();
    for (int o = tid; o < 960; o += 256) {
        float s = b2[o];
#pragma unroll
        for (int k = 0; k < 40; k++) s += hs[k] * w2[o * 40 + k];
        g_cw[b * 960 + o] = 1.0f / (1.0f + expf(-s));
    }
}

__device__ __forceinline__ float jsig(float z) { return 1.0f / (1.0f + expf(-z)); }

// kappa: one block per (m, output); thread = one (u,v) term; double tree-reduce.
__global__ void k_prep(const float* __restrict__ lcp, const float* __restrict__ hcp) {
    __shared__ double ctab[16];
    __shared__ double red[256];
    int tid = threadIdx.x;
    if (tid < 16) ctab[tid] = cos((double)tid * 3.14159265358979323846 / 8.0);
    __syncthreads();
    float lc = *lcp, hc = *hcp;
    int bx = blockIdx.x;
    int m = bx >> 8, t = bx & 255;
    int a = t >> 4, bb = t & 15;
    int u = tid >> 4, v = tid & 15;
    float step = __fdiv_rn(2.0f, 15.0f);
    int s = (u + 8) & 15, t2 = (v + 8) & 15;
    float yv = __fadd_rn(__fmul_rn((float)s, step), -1.0f);
    float xv = __fadd_rn(__fmul_rn((float)t2, step), -1.0f);
    float d2 = __fadd_rn(__fmul_rn(xv, xv), __fmul_rn(yv, yv));
    float d = __fdiv_rn(__fsqrt_rn(d2), 1.4142135623730951f);
    float mv;
    if (m == 0) {
        mv = jsig(__fdiv_rn(__fsub_rn(lc, d), 1e-6f));
    } else {
        float m1 = jsig(__fdiv_rn(__fsub_rn(d, lc), 1e-6f));
        float m2 = jsig(__fdiv_rn(__fsub_rn(hc, d), 1e-6f));
        mv = m1 * m2;
    }
    int ph = (u * a + v * bb) & 15;
    red[tid] = (double)mv * ctab[ph];
    __syncthreads();
    for (int off = 128; off > 0; off >>= 1) {
        if (tid < off) red[tid] += red[tid + off];
        __syncthreads();
    }
    if (tid == 0) g_kappa[m][t] = (float)(red[0] * (1.0 / 256.0));
}

// band GEMM (round-8 scalar form, known good)
__global__ __launch_bounds__(256) void k_band(const float* __restrict__ x) {
    __shared__ float As[64][32];
    __shared__ float Bs[32][256];
    __shared__ float ks[256];
    int m = blockIdx.y;
    int rows0 = blockIdx.x * 64;
    int tid = threadIdx.x;
    ks[tid] = g_kappa[m][tid];
    int tr = tid >> 5, tp = tid & 31;
    float acc[8][8];
#pragma unroll
    for (int i = 0; i < 8; i++)
#pragma unroll
        for (int j = 0; j < 8; j++) acc[i][j] = 0.f;
    int rl = tid >> 2, qo = (tid & 3) * 8;
    for (int kq = 0; kq < 256; kq += 32) {
        __syncthreads();
        const float4* src = (const float4*)(x + (size_t)(rows0 + rl) * 256 + kq + qo);
        float4 a0 = src[0], a1 = src[1];
        *((float4*)&As[rl][qo]) = a0;
        *((float4*)&As[rl][qo + 4]) = a1;
#pragma unroll
        for (int it = 0; it < 32; it++) {
            int q = kq + it, p = tid;
            int aa = ((p >> 4) - (q >> 4)) & 15;
            int bbq = ((p & 15) - (q & 15)) & 15;
            Bs[it][p] = ks[aa * 16 + bbq];
        }
        __syncthreads();
#pragma unroll
        for (int ql = 0; ql < 32; ql++) {
            float av[8], bv[8];
#pragma unroll
            for (int i = 0; i < 8; i++) av[i] = As[tr * 8 + i][ql];
#pragma unroll
            for (int j = 0; j < 8; j++) bv[j] = Bs[ql][tp + 32 * j];
#pragma unroll
            for (int i = 0; i < 8; i++)
#pragma unroll
                for (int j = 0; j < 8; j++) acc[i][j] = fmaf(av[i], bv[j], acc[i][j]);
        }
    }
    float* outp = g_bands[m];
#pragma unroll
    for (int i = 0; i < 8; i++) {
        size_t ro = (size_t)(rows0 + tr * 8 + i) * 256;
#pragma unroll
        for (int j = 0; j < 8; j++) outp[ro + tp + 32 * j] = acc[i][j];
    }
}

__global__ void k_high(const float* __restrict__ x) {
    size_t i = (size_t)blockIdx.x * 256 + threadIdx.x;
    float4 xv = ((const float4*)x)[i];
    float4 b0 = ((const float4*)g_bands[0])[i];
    float4 b1 = ((const float4*)g_bands[1])[i];
    float4 r;
    r.x = xv.x - b0.x - b1.x; r.y = xv.y - b0.y - b1.y;
    r.z = xv.z - b0.z - b1.z; r.w = xv.w - b0.w - b1.w;
    ((float4*)g_bands[2])[i] = r;
}

// weight prep: f32 -> f16 blocks [m][cotile][chunk][tap][k16][co64]
__global__ void k_wprep(const float* __restrict__ wl, const float* __restrict__ wm,
                        const float* __restrict__ wh) {
    int chunk = blockIdx.x, cotile = blockIdx.y, m = blockIdx.z;
    const float* W = (m == 0) ? wl : ((m == 1) ? wm : wh);
    size_t base = ((size_t)(m * 5 + cotile) * 20 + chunk) * 9216;
    for (int i = threadIdx.x; i < 9216; i += 256) {
        int co = i & 63, k = (i >> 6) & 15, tap = i >> 10;
        float w = W[(size_t)(cotile * 64 + co) * 2880 + (chunk * 16 + k) * 9 + tap];
        g_Wh[base + (size_t)tap * 1024 + k * 64 + co] = __float2half_rn(w);
    }
}

// ---------------------------------------------------------------------------
// single-pass f16 mma.sync conv + bias + GroupNorm + affine + residual.
// grid (5 cotile, 128 b, 3 m), block 256 (8 warps).
// X smem: [324 px][16 ci] f16, 48B pitch.  W smem: [tap9*k16 rows][co64], 144B pitch.
#define XHOFF 0
#define WSOFF 15552
#define REDOF 36288
#define STAOF 38336
#define DYNSM 38400

__global__ void __launch_bounds__(256, 2) k_conv(
    const float* __restrict__ x,
    const float* __restrict__ bl, const float* __restrict__ gl, const float* __restrict__ el,
    const float* __restrict__ bm, const float* __restrict__ gm, const float* __restrict__ em,
    const float* __restrict__ bh, const float* __restrict__ gh, const float* __restrict__ eh) {
    extern __shared__ char P[];
    uint32_t Pu = s2u(P);
    int tid = threadIdx.x;
    int cotile = blockIdx.x, b = blockIdx.y, m = blockIdx.z;
    const float* biasp = (m == 0) ? bl : ((m == 1) ? bm : bh);
    const float* gamp  = (m == 0) ? gl : ((m == 1) ? gm : gh);
    const float* betp  = (m == 0) ? el : ((m == 1) ? em : eh);
    const float* src = g_bands[m];

    for (int i = tid * 16; i < 15552; i += 4096)
        *(uint4*)(P + i) = make_uint4(0, 0, 0, 0);

    int lane = tid & 31, wid = tid >> 5;
    int wq = wid & 3, chh = wid >> 2;
    uint32_t laneA[4];
#pragma unroll
    for (int mf = 0; mf < 4; mf++)
        laneA[mf] = Pu + XHOFF +
            (uint32_t)(((wq * 4 + mf) * 18 + (lane & 15)) * 48) + ((lane >> 4) * 16);

    float acc[4][4][4];
#pragma unroll
    for (int a = 0; a < 4; a++)
#pragma unroll
        for (int n = 0; n < 4; n++)
#pragma unroll
            for (int r = 0; r < 4; r++) acc[a][n][r] = 0.f;

    const size_t bimg = (size_t)b * 81920;
    const uint4* wblock = (const uint4*)(const void*)(g_Wh +
        ((size_t)(m * 5 + cotile) * 20) * 9216);

    for (int c = 0; c < 20; c++) {
        __syncthreads();
        {   // X tile: thread = pixel; 16 ci values f16
            int px = tid, r = px >> 4, cc = px & 15;
            uint32_t rowb = (uint32_t)(((r + 1) * 18 + (cc + 1)) * 48);
            const float* sp = src + bimg + (size_t)c * 16 * 256 + px;
            uint32_t hv[8];
#pragma unroll
            for (int j = 0; j < 8; j++) {
                float v0 = sp[(size_t)(2 * j) * 256];
                float v1 = sp[(size_t)(2 * j + 1) * 256];
                hv[j] = (uint32_t)__half_as_ushort(__float2half_rn(v0)) |
                        ((uint32_t)__half_as_ushort(__float2half_rn(v1)) << 16);
            }
            *(uint4*)(P + XHOFF + rowb)      = make_uint4(hv[0], hv[1], hv[2], hv[3]);
            *(uint4*)(P + XHOFF + rowb + 16) = make_uint4(hv[4], hv[5], hv[6], hv[7]);
        }
        {   // W tile: contiguous 18432B block (1152 uint4) -> smem rows pitch 144
            const uint4* wsrc = wblock + (size_t)c * 1152;
#pragma unroll
            for (int i = tid; i < 1152; i += 256) {
                uint4 v = wsrc[i];
                *(uint4*)(P + WSOFF + (i >> 3) * 144 + (i & 7) * 16) = v;
            }
        }
        __syncthreads();

#pragma unroll
        for (int tap = 0; tap < 9; tap++) {
            uint32_t aoff = (uint32_t)(((tap / 3) * 18 + (tap % 3)) * 48);
            uint32_t bf[4][2];
#pragma unroll
            for (int t16 = 0; t16 < 2; t16++) {
                uint32_t baddr = Pu + WSOFF + (uint32_t)(tap * 2304 +
                    (lane & 15) * 144 + (chh * 32 + t16 * 16) * 2 + (lane >> 4) * 16);
                uint32_t r0, r1, r2, r3;
                asm volatile(
                    "ldmatrix.sync.aligned.m8n8.x4.trans.shared.b16 {%0,%1,%2,%3}, [%4];"
                    : "=r"(r0), "=r"(r1), "=r"(r2), "=r"(r3) : "r"(baddr));
                bf[t16 * 2][0] = r0; bf[t16 * 2][1] = r1;
                bf[t16 * 2 + 1][0] = r2; bf[t16 * 2 + 1][1] = r3;
            }
#pragma unroll
            for (int mf = 0; mf < 4; mf++) {
                uint32_t a0, a1, a2, a3;
                asm volatile(
                    "ldmatrix.sync.aligned.m8n8.x4.shared.b16 {%0,%1,%2,%3}, [%4];"
                    : "=r"(a0), "=r"(a1), "=r"(a2), "=r"(a3)
                    : "r"(laneA[mf] + aoff));
#pragma unroll
                for (int nf = 0; nf < 4; nf++)
                    asm volatile(
                        "mma.sync.aligned.m16n8k16.row.col.f32.f16.f16.f32 "
                        "{%0,%1,%2,%3}, {%4,%5,%6,%7}, {%8,%9}, {%0,%1,%2,%3};"
                        : "+f"(acc[mf][nf][0]), "+f"(acc[mf][nf][1]),
                          "+f"(acc[mf][nf][2]), "+f"(acc[mf][nf][3])
                        : "r"(a0), "r"(a1), "r"(a2), "r"(a3),
                          "r"(bf[nf][0]), "r"(bf[nf][1]));
            }
        }
    }

    // ---- epilogue ----
    int co_base = cotile * 64 + chh * 32;
    float bias2[4][2];
#pragma unroll
    for (int nf = 0; nf < 4; nf++) {
        int co0 = co_base + nf * 8 + 2 * (lane & 3);
        bias2[nf][0] = biasp[co0];
        bias2[nf][1] = biasp[co0 + 1];
    }
    float s = 0.f, q = 0.f;
#pragma unroll
    for (int mf = 0; mf < 4; mf++)
#pragma unroll
        for (int nf = 0; nf < 4; nf++)
#pragma unroll
            for (int r = 0; r < 4; r++) {
                float v = acc[mf][nf][r] + bias2[nf][r & 1];
                s += v; q += v * v;
            }
    float* red_s = (float*)(P + REDOF);
    float* red_q = red_s + 256;
    red_s[tid] = s; red_q[tid] = q;
    __syncthreads();
    for (int off = 128; off > 0; off >>= 1) {
        if (tid < off) { red_s[tid] += red_s[tid + off]; red_q[tid] += red_q[tid + off]; }
        __syncthreads();
    }
    float* stat = (float*)(P + STAOF);
    if (tid == 0) {
        float mu = red_s[0] * (1.f / 16384.f);
        float var = red_q[0] * (1.f / 16384.f) - mu * mu;
        stat[0] = mu;
        stat[1] = rsqrtf(var + 1e-5f);
    }
    __syncthreads();
    float mu = stat[0], rs = stat[1];
    float* feat = g_feat[m];
#pragma unroll
    for (int nf = 0; nf < 4; nf++) {
        int co0 = co_base + nf * 8 + 2 * (lane & 3);
        float ga0 = gamp[co0], be0 = betp[co0];
        float ga1 = gamp[co0 + 1], be1 = betp[co0 + 1];
#pragma unroll
        for (int mf = 0; mf < 4; mf++) {
            int px0 = wq * 64 + mf * 16 + (lane >> 2);
#pragma unroll
            for (int r = 0; r < 4; r++) {
                int px = px0 + ((r >= 2) ? 8 : 0);
                int co = co0 + (r & 1);
                float v = acc[mf][nf][r] + bias2[nf][r & 1];
                float ga = (r & 1) ? ga1 : ga0;
                float be = (r & 1) ? be1 : be0;
                size_t o = bimg + (size_t)co * 256 + px;
                feat[o] = (v - mu) * rs * ga + be + x[o];
            }
        }
    }
}

// ---------------------------------------------------------------------------
__global__ void k_fuse(const float* __restrict__ saw, const float* __restrict__ sab,
                       float* __restrict__ out) {
    __shared__ float cw_s[960];
    __shared__ float saw_s[320];
    int b = blockIdx.x, p = threadIdx.x;
    for (int e = p; e < 960; e += 256) cw_s[e] = g_cw[b * 960 + e];
    for (int e = p; e < 320; e += 256) saw_s[e] = saw[e];
    __syncthreads();
    size_t base = (size_t)b * 81920 + p;
    float sacc = 0.f;
    for (int c = 0; c < 320; c++) {
        size_t o = base + (size_t)c * 256;
        float f = cw_s[c] * g_feat[0][o] + cw_s[320 + c] * g_feat[1][o]
                + cw_s[640 + c] * g_feat[2][o];
        sacc += f * saw_s[c];
    }
    float sw = 1.0f / (1.0f + expf(-(sacc + sab[0])));
    for (int c = 0; c < 320; c++) {
        size_t o = base + (size_t)c * 256;
        float f = cw_s[c] * g_feat[0][o] + cw_s[320 + c] * g_feat[1][o]
                + cw_s[640 + c] * g_feat[2][o];
        out[o] = f * sw;
    }
}

// ---------------------------------------------------------------------------
extern "C" void kernel_launch(void* const* d_in, const int* in_sizes, int n_in,
                              void* d_out, int out_size) {
    const float* x   = (const float*)d_in[0];
    const float* lc  = (const float*)d_in[1];
    const float* hc  = (const float*)d_in[2];
    const float* w1  = (const float*)d_in[3];
    const float* b1  = (const float*)d_in[4];
    const float* w2  = (const float*)d_in[5];
    const float* b2  = (const float*)d_in[6];
    const float* wl  = (const float*)d_in[7];
    const float* bl  = (const float*)d_in[8];
    const float* gl  = (const float*)d_in[9];
    const float* el  = (const float*)d_in[10];
    const float* wm  = (const float*)d_in[11];
    const float* bm  = (const float*)d_in[12];
    const float* gm  = (const float*)d_in[13];
    const float* em  = (const float*)d_in[14];
    const float* wh  = (const float*)d_in[15];
    const float* bh  = (const float*)d_in[16];
    const float* gh  = (const float*)d_in[17];
    const float* eh  = (const float*)d_in[18];
    const float* saw = (const float*)d_in[19];
    const float* sab = (const float*)d_in[20];
    float* out = (float*)d_out;

    static int smset = 0;
    if (!smset) {
        cudaFuncSetAttribute(k_conv, cudaFuncAttributeMaxDynamicSharedMemorySize, DYNSM);
        smset = 1;
    }

    k_wprep<<<dim3(20, 5, 3), 256>>>(wl, wm, wh);
    k_avg  <<<dim3(128, 40), 256>>>(x);
    k_ca   <<<128, 256>>>(w1, b1, w2, b2);
    k_prep <<<512, 256>>>(lc, hc);
    k_band <<<dim3(640, 2), 256>>>(x);
    k_high <<<10240, 256>>>(x);
    k_conv <<<dim3(5, 128, 3), 256, DYNSM>>>(x, bl, gl, el, bm, gm, em, bh, gh, eh);
    k_fuse <<<128, 256>>>(saw, sab, out);
}

// round 15
// speedup vs baseline: 5.8253x; 1.1794x over previous
#include <cuda_runtime.h>
#include <cuda_fp16.h>
#include <math.h>
#include <stdint.h>

#define SZ 10485760
__device__ float g_bands[3][SZ];     // low, mid, high
__device__ float g_feat[3][SZ];
__device__ float g_avg[40960];
__device__ float g_cw[128 * 960];
__device__ float g_kappa[2][256];
__device__ __align__(16) __half g_Wh[2764800];   // [m][cotile][chunk][tap][k16][co64]
__device__ __align__(16) __half g_Kh[2][65536];  // circulant K hi  [m][q][p]
__device__ __align__(16) __half g_Kl[2][65536];  // circulant K lo

__device__ __forceinline__ uint32_t s2u(const void* p) {
    uint32_t a;
    asm("{ .reg .u64 t; cvta.to.shared.u64 t, %1; cvt.u32.u64 %0, t; }" : "=r"(a) : "l"(p));
    return a;
}

// ---------------------------------------------------------------------------
__global__ void k_avg(const float* __restrict__ x) {
    int b = blockIdx.x;
    int c = blockIdx.y * 8 + (threadIdx.x >> 5);
    int lane = threadIdx.x & 31;
    const float* px = x + ((size_t)b * 320 + c) * 256;
    float s = 0.f;
#pragma unroll
    for (int i = 0; i < 8; i++) s += px[lane + 32 * i];
#pragma unroll
    for (int o = 16; o > 0; o >>= 1) s += __shfl_xor_sync(0xffffffffu, s, o);
    if (lane == 0) g_avg[b * 320 + c] = s * (1.0f / 256.0f);
}

__global__ void k_ca(const float* __restrict__ w1, const float* __restrict__ b1,
                     const float* __restrict__ w2, const float* __restrict__ b2) {
    __shared__ float av[320];
    __shared__ float hs[40];
    int b = blockIdx.x, tid = threadIdx.x;
    for (int e = tid; e < 320; e += 256) av[e] = g_avg[b * 320 + e];
    __syncthreads();
    if (tid < 40) {
        float s = b1[tid];
        for (int c = 0; c < 320; c++) s += av[c] * w1[tid * 320 + c];
        hs[tid] = fmaxf(s, 0.0f);
    }
    __syncthreads();
    for (int o = tid; o < 960; o += 256) {
        float s = b2[o];
#pragma unroll
        for (int k = 0; k < 40; k++) s += hs[k] * w2[o * 40 + k];
        g_cw[b * 960 + o] = 1.0f / (1.0f + expf(-s));
    }
}

__device__ __forceinline__ float jsig(float z) { return 1.0f / (1.0f + expf(-z)); }

// kappa: one block per (m, output); thread = one (u,v) term; double tree-reduce.
__global__ void k_prep(const float* __restrict__ lcp, const float* __restrict__ hcp) {
    __shared__ double ctab[16];
    __shared__ double red[256];
    int tid = threadIdx.x;
    if (tid < 16) ctab[tid] = cos((double)tid * 3.14159265358979323846 / 8.0);
    __syncthreads();
    float lc = *lcp, hc = *hcp;
    int bx = blockIdx.x;
    int m = bx >> 8, t = bx & 255;
    int a = t >> 4, bb = t & 15;
    int u = tid >> 4, v = tid & 15;
    float step = __fdiv_rn(2.0f, 15.0f);
    int s = (u + 8) & 15, t2 = (v + 8) & 15;
    float yv = __fadd_rn(__fmul_rn((float)s, step), -1.0f);
    float xv = __fadd_rn(__fmul_rn((float)t2, step), -1.0f);
    float d2 = __fadd_rn(__fmul_rn(xv, xv), __fmul_rn(yv, yv));
    float d = __fdiv_rn(__fsqrt_rn(d2), 1.4142135623730951f);
    float mv;
    if (m == 0) {
        mv = jsig(__fdiv_rn(__fsub_rn(lc, d), 1e-6f));
    } else {
        float m1 = jsig(__fdiv_rn(__fsub_rn(d, lc), 1e-6f));
        float m2 = jsig(__fdiv_rn(__fsub_rn(hc, d), 1e-6f));
        mv = m1 * m2;
    }
    int ph = (u * a + v * bb) & 15;
    red[tid] = (double)mv * ctab[ph];
    __syncthreads();
    for (int off = 128; off > 0; off >>= 1) {
        if (tid < off) red[tid] += red[tid + off];
        __syncthreads();
    }
    if (tid == 0) g_kappa[m][t] = (float)(red[0] * (1.0 / 256.0));
}

// circulant matrix K[q][p] (f16 hi/lo) from kappa
__global__ void k_kmat(int dummy) {
    int q = blockIdx.x, m = blockIdx.y, p = threadIdx.x;
    int aa = ((((p >> 4) - (q >> 4)) & 15) << 4) | (((p & 15) - (q & 15)) & 15);
    float val = g_kappa[m][aa];
    __half h = __float2half_rn(val);
    g_Kh[m][q * 256 + p] = h;
    g_Kl[m][q * 256 + p] = __float2half_rn(val - __half2float(h));
}

// ---------------------------------------------------------------------------
// band GEMM via mma.sync, hi/lo split (3 passes). grid (640, 2), block 256.
// Block tile: 64 rows x 256 p, K=256 in 16-chunks. Warp: 16 rows x 128 p.
#define BA_AH 0
#define BA_AL 3072
#define BA_BH 6144
#define BA_BL 14592
#define BA_SM 23040

__global__ void __launch_bounds__(256, 2) k_band2(const float* __restrict__ x) {
    __shared__ char P[BA_SM];
    uint32_t Pu = s2u(P);
    int tid = threadIdx.x;
    int m = blockIdx.y;
    int rows0 = blockIdx.x * 64;
    int lane = tid & 31, wid = tid >> 5;
    int rw = wid & 3, nh = wid >> 2;

    float acc[16][4];
#pragma unroll
    for (int f = 0; f < 16; f++)
#pragma unroll
        for (int r = 0; r < 4; r++) acc[f][r] = 0.f;

    int arow = tid >> 2, aqg = (tid & 3) * 4;
    const uint32_t* Kh2 = (const uint32_t*)(const void*)g_Kh[m];
    const uint32_t* Kl2 = (const uint32_t*)(const void*)g_Kl[m];
    int bk = tid >> 7, bn2 = tid & 127;

    uint32_t aAddrH = Pu + BA_AH + (uint32_t)((rw * 16 + (lane & 15)) * 48) + ((lane >> 4) * 16);
    uint32_t aAddrL = aAddrH + (BA_AL - BA_AH);

    for (int kc = 0; kc < 16; kc++) {
        int q0 = kc * 16;
        __syncthreads();
        {   // A tile 64x16 f32 -> hi/lo f16
            float4 v = *(const float4*)(x + (size_t)(rows0 + arow) * 256 + q0 + aqg);
            __half hx = __float2half_rn(v.x), hy = __float2half_rn(v.y);
            __half hz = __float2half_rn(v.z), hw = __float2half_rn(v.w);
            uint2 hv, lv;
            hv.x = (uint32_t)__half_as_ushort(hx) | ((uint32_t)__half_as_ushort(hy) << 16);
            hv.y = (uint32_t)__half_as_ushort(hz) | ((uint32_t)__half_as_ushort(hw) << 16);
            __half lx = __float2half_rn(v.x - __half2float(hx));
            __half ly = __float2half_rn(v.y - __half2float(hy));
            __half lz = __float2half_rn(v.z - __half2float(hz));
            __half lw = __float2half_rn(v.w - __half2float(hw));
            lv.x = (uint32_t)__half_as_ushort(lx) | ((uint32_t)__half_as_ushort(ly) << 16);
            lv.y = (uint32_t)__half_as_ushort(lz) | ((uint32_t)__half_as_ushort(lw) << 16);
            *(uint2*)(P + BA_AH + arow * 48 + aqg * 2) = hv;
            *(uint2*)(P + BA_AL + arow * 48 + aqg * 2) = lv;
        }
        {   // B tile 16x256 f16 hi/lo from precomputed K
#pragma unroll
            for (int kk = 0; kk < 8; kk++) {
                int k = kk * 2 + bk;
                uint32_t vh = Kh2[(q0 + k) * 128 + bn2];
                uint32_t vl = Kl2[(q0 + k) * 128 + bn2];
                *(uint32_t*)(P + BA_BH + k * 528 + bn2 * 4) = vh;
                *(uint32_t*)(P + BA_BL + k * 528 + bn2 * 4) = vl;
            }
        }
        __syncthreads();
        uint32_t ah0, ah1, ah2, ah3, al0, al1, al2, al3;
        asm volatile("ldmatrix.sync.aligned.m8n8.x4.shared.b16 {%0,%1,%2,%3}, [%4];"
                     : "=r"(ah0), "=r"(ah1), "=r"(ah2), "=r"(ah3) : "r"(aAddrH));
        asm volatile("ldmatrix.sync.aligned.m8n8.x4.shared.b16 {%0,%1,%2,%3}, [%4];"
                     : "=r"(al0), "=r"(al1), "=r"(al2), "=r"(al3) : "r"(aAddrL));
#pragma unroll
        for (int nb = 0; nb < 8; nb++) {
            int n16 = nh * 128 + nb * 16;
            uint32_t bAddr = Pu + BA_BH + (uint32_t)((lane & 15) * 528 + n16 * 2 + (lane >> 4) * 16);
            uint32_t bh0, bh1, bh2, bh3, bl0, bl1, bl2, bl3;
            asm volatile("ldmatrix.sync.aligned.m8n8.x4.trans.shared.b16 {%0,%1,%2,%3}, [%4];"
                         : "=r"(bh0), "=r"(bh1), "=r"(bh2), "=r"(bh3) : "r"(bAddr));
            asm volatile("ldmatrix.sync.aligned.m8n8.x4.trans.shared.b16 {%0,%1,%2,%3}, [%4];"
                         : "=r"(bl0), "=r"(bl1), "=r"(bl2), "=r"(bl3)
                         : "r"(bAddr + (uint32_t)(BA_BL - BA_BH)));
            float* A0 = acc[2 * nb];
            float* A1 = acc[2 * nb + 1];
#define BMMA(AC, x0, x1, x2, x3, y0, y1)                                      \
            asm volatile("mma.sync.aligned.m16n8k16.row.col.f32.f16.f16.f32 " \
                "{%0,%1,%2,%3}, {%4,%5,%6,%7}, {%8,%9}, {%0,%1,%2,%3};"       \
                : "+f"((AC)[0]), "+f"((AC)[1]), "+f"((AC)[2]), "+f"((AC)[3])  \
                : "r"(x0), "r"(x1), "r"(x2), "r"(x3), "r"(y0), "r"(y1))
            BMMA(A0, ah0, ah1, ah2, ah3, bh0, bh1);
            BMMA(A0, ah0, ah1, ah2, ah3, bl0, bl1);
            BMMA(A0, al0, al1, al2, al3, bh0, bh1);
            BMMA(A1, ah0, ah1, ah2, ah3, bh2, bh3);
            BMMA(A1, ah0, ah1, ah2, ah3, bl2, bl3);
            BMMA(A1, al0, al1, al2, al3, bh2, bh3);
#undef BMMA
        }
    }
    float* outp = g_bands[m];
    int row = rows0 + rw * 16 + (lane >> 2);
#pragma unroll
    for (int f = 0; f < 16; f++) {
        int p0 = nh * 128 + f * 8 + (lane & 3) * 2;
        *(float2*)(outp + (size_t)row * 256 + p0) = make_float2(acc[f][0], acc[f][1]);
        *(float2*)(outp + (size_t)(row + 8) * 256 + p0) = make_float2(acc[f][2], acc[f][3]);
    }
}

__global__ void k_high(const float* __restrict__ x) {
    size_t i = (size_t)blockIdx.x * 256 + threadIdx.x;
    float4 xv = ((const float4*)x)[i];
    float4 b0 = ((const float4*)g_bands[0])[i];
    float4 b1 = ((const float4*)g_bands[1])[i];
    float4 r;
    r.x = xv.x - b0.x - b1.x; r.y = xv.y - b0.y - b1.y;
    r.z = xv.z - b0.z - b1.z; r.w = xv.w - b0.w - b1.w;
    ((float4*)g_bands[2])[i] = r;
}

// weight prep: f32 -> f16 blocks [m][cotile][chunk][tap][k16][co64]
__global__ void k_wprep(const float* __restrict__ wl, const float* __restrict__ wm,
                        const float* __restrict__ wh) {
    int chunk = blockIdx.x, cotile = blockIdx.y, m = blockIdx.z;
    const float* W = (m == 0) ? wl : ((m == 1) ? wm : wh);
    size_t base = ((size_t)(m * 5 + cotile) * 20 + chunk) * 9216;
    for (int i = threadIdx.x; i < 9216; i += 256) {
        int co = i & 63, k = (i >> 6) & 15, tap = i >> 10;
        float w = W[(size_t)(cotile * 64 + co) * 2880 + (chunk * 16 + k) * 9 + tap];
        g_Wh[base + (size_t)tap * 1024 + k * 64 + co] = __float2half_rn(w);
    }
}

// ---------------------------------------------------------------------------
// single-pass f16 mma.sync conv + bias + GroupNorm + affine + residual.
// grid (5 cotile, 128 b, 3 m), block 256 (8 warps).
// X smem: [324 px][16 ci] f16, 48B pitch.  W smem: [tap9*k16 rows][co64], 144B pitch.
#define XHOFF 0
#define WSOFF 15552
#define REDOF 36288
#define STAOF 38336
#define DYNSM 38400

__global__ void __launch_bounds__(256, 2) k_conv(
    const float* __restrict__ x,
    const float* __restrict__ bl, const float* __restrict__ gl, const float* __restrict__ el,
    const float* __restrict__ bm, const float* __restrict__ gm, const float* __restrict__ em,
    const float* __restrict__ bh, const float* __restrict__ gh, const float* __restrict__ eh) {
    extern __shared__ char P[];
    uint32_t Pu = s2u(P);
    int tid = threadIdx.x;
    int cotile = blockIdx.x, b = blockIdx.y, m = blockIdx.z;
    const float* biasp = (m == 0) ? bl : ((m == 1) ? bm : bh);
    const float* gamp  = (m == 0) ? gl : ((m == 1) ? gm : gh);
    const float* betp  = (m == 0) ? el : ((m == 1) ? em : eh);
    const float* src = g_bands[m];

    for (int i = tid * 16; i < 15552; i += 4096)
        *(uint4*)(P + i) = make_uint4(0, 0, 0, 0);

    int lane = tid & 31, wid = tid >> 5;
    int wq = wid & 3, chh = wid >> 2;
    uint32_t laneA[4];
#pragma unroll
    for (int mf = 0; mf < 4; mf++)
        laneA[mf] = Pu + XHOFF +
            (uint32_t)(((wq * 4 + mf) * 18 + (lane & 15)) * 48) + ((lane >> 4) * 16);

    float acc[4][4][4];
#pragma unroll
    for (int a = 0; a < 4; a++)
#pragma unroll
        for (int n = 0; n < 4; n++)
#pragma unroll
            for (int r = 0; r < 4; r++) acc[a][n][r] = 0.f;

    const size_t bimg = (size_t)b * 81920;
    const uint4* wblock = (const uint4*)(const void*)(g_Wh +
        ((size_t)(m * 5 + cotile) * 20) * 9216);

    for (int c = 0; c < 20; c++) {
        __syncthreads();
        {   // X tile: thread = pixel; 16 ci values f16
            int px = tid, r = px >> 4, cc = px & 15;
            uint32_t rowb = (uint32_t)(((r + 1) * 18 + (cc + 1)) * 48);
            const float* sp = src + bimg + (size_t)c * 16 * 256 + px;
            uint32_t hv[8];
#pragma unroll
            for (int j = 0; j < 8; j++) {
                float v0 = sp[(size_t)(2 * j) * 256];
                float v1 = sp[(size_t)(2 * j + 1) * 256];
                hv[j] = (uint32_t)__half_as_ushort(__float2half_rn(v0)) |
                        ((uint32_t)__half_as_ushort(__float2half_rn(v1)) << 16);
            }
            *(uint4*)(P + XHOFF + rowb)      = make_uint4(hv[0], hv[1], hv[2], hv[3]);
            *(uint4*)(P + XHOFF + rowb + 16) = make_uint4(hv[4], hv[5], hv[6], hv[7]);
        }
        {   // W tile: contiguous 18432B block (1152 uint4) -> smem rows pitch 144
            const uint4* wsrc = wblock + (size_t)c * 1152;
#pragma unroll
            for (int i = tid; i < 1152; i += 256) {
                uint4 v = wsrc[i];
                *(uint4*)(P + WSOFF + (i >> 3) * 144 + (i & 7) * 16) = v;
            }
        }
        __syncthreads();

#pragma unroll
        for (int tap = 0; tap < 9; tap++) {
            uint32_t aoff = (uint32_t)(((tap / 3) * 18 + (tap % 3)) * 48);
            uint32_t bf[4][2];
#pragma unroll
            for (int t16 = 0; t16 < 2; t16++) {
                uint32_t baddr = Pu + WSOFF + (uint32_t)(tap * 2304 +
                    (lane & 15) * 144 + (chh * 32 + t16 * 16) * 2 + (lane >> 4) * 16);
                uint32_t r0, r1, r2, r3;
                asm volatile(
                    "ldmatrix.sync.aligned.m8n8.x4.trans.shared.b16 {%0,%1,%2,%3}, [%4];"
                    : "=r"(r0), "=r"(r1), "=r"(r2), "=r"(r3) : "r"(baddr));
                bf[t16 * 2][0] = r0; bf[t16 * 2][1] = r1;
                bf[t16 * 2 + 1][0] = r2; bf[t16 * 2 + 1][1] = r3;
            }
#pragma unroll
            for (int mf = 0; mf < 4; mf++) {
                uint32_t a0, a1, a2, a3;
                asm volatile(
                    "ldmatrix.sync.aligned.m8n8.x4.shared.b16 {%0,%1,%2,%3}, [%4];"
                    : "=r"(a0), "=r"(a1), "=r"(a2), "=r"(a3)
                    : "r"(laneA[mf] + aoff));
#pragma unroll
                for (int nf = 0; nf < 4; nf++)
                    asm volatile(
                        "mma.sync.aligned.m16n8k16.row.col.f32.f16.f16.f32 "
                        "{%0,%1,%2,%3}, {%4,%5,%6,%7}, {%8,%9}, {%0,%1,%2,%3};"
                        : "+f"(acc[mf][nf][0]), "+f"(acc[mf][nf][1]),
                          "+f"(acc[mf][nf][2]), "+f"(acc[mf][nf][3])
                        : "r"(a0), "r"(a1), "r"(a2), "r"(a3),
                          "r"(bf[nf][0]), "r"(bf[nf][1]));
            }
        }
    }

    // ---- epilogue ----
    int co_base = cotile * 64 + chh * 32;
    float bias2[4][2];
#pragma unroll
    for (int nf = 0; nf < 4; nf++) {
        int co0 = co_base + nf * 8 + 2 * (lane & 3);
        bias2[nf][0] = biasp[co0];
        bias2[nf][1] = biasp[co0 + 1];
    }
    float s = 0.f, q = 0.f;
#pragma unroll
    for (int mf = 0; mf < 4; mf++)
#pragma unroll
        for (int nf = 0; nf < 4; nf++)
#pragma unroll
            for (int r = 0; r < 4; r++) {
                float v = acc[mf][nf][r] + bias2[nf][r & 1];
                s += v; q += v * v;
            }
    float* red_s = (float*)(P + REDOF);
    float* red_q = red_s + 256;
    red_s[tid] = s; red_q[tid] = q;
    __syncthreads();
    for (int off = 128; off > 0; off >>= 1) {
        if (tid < off) { red_s[tid] += red_s[tid + off]; red_q[tid] += red_q[tid + off]; }
        __syncthreads();
    }
    float* stat = (float*)(P + STAOF);
    if (tid == 0) {
        float mu = red_s[0] * (1.f / 16384.f);
        float var = red_q[0] * (1.f / 16384.f) - mu * mu;
        stat[0] = mu;
        stat[1] = rsqrtf(var + 1e-5f);
    }
    __syncthreads();
    float mu = stat[0], rs = stat[1];
    float* feat = g_feat[m];
#pragma unroll
    for (int nf = 0; nf < 4; nf++) {
        int co0 = co_base + nf * 8 + 2 * (lane & 3);
        float ga0 = gamp[co0], be0 = betp[co0];
        float ga1 = gamp[co0 + 1], be1 = betp[co0 + 1];
#pragma unroll
        for (int mf = 0; mf < 4; mf++) {
            int px0 = wq * 64 + mf * 16 + (lane >> 2);
#pragma unroll
            for (int r = 0; r < 4; r++) {
                int px = px0 + ((r >= 2) ? 8 : 0);
                int co = co0 + (r & 1);
                float v = acc[mf][nf][r] + bias2[nf][r & 1];
                float ga = (r & 1) ? ga1 : ga0;
                float be = (r & 1) ? be1 : be0;
                size_t o = bimg + (size_t)co * 256 + px;
                feat[o] = (v - mu) * rs * ga + be + x[o];
            }
        }
    }
}

// ---------------------------------------------------------------------------
__global__ void k_fuse(const float* __restrict__ saw, const float* __restrict__ sab,
                       float* __restrict__ out) {
    __shared__ float cw_s[960];
    __shared__ float saw_s[320];
    int b = blockIdx.x, p = threadIdx.x;
    for (int e = p; e < 960; e += 256) cw_s[e] = g_cw[b * 960 + e];
    for (int e = p; e < 320; e += 256) saw_s[e] = saw[e];
    __syncthreads();
    size_t base = (size_t)b * 81920 + p;
    float sacc = 0.f;
    for (int c = 0; c < 320; c++) {
        size_t o = base + (size_t)c * 256;
        float f = cw_s[c] * g_feat[0][o] + cw_s[320 + c] * g_feat[1][o]
                + cw_s[640 + c] * g_feat[2][o];
        sacc += f * saw_s[c];
    }
    float sw = 1.0f / (1.0f + expf(-(sacc + sab[0])));
    for (int c = 0; c < 320; c++) {
        size_t o = base + (size_t)c * 256;
        float f = cw_s[c] * g_feat[0][o] + cw_s[320 + c] * g_feat[1][o]
                + cw_s[640 + c] * g_feat[2][o];
        out[o] = f * sw;
    }
}

// ---------------------------------------------------------------------------
extern "C" void kernel_launch(void* const* d_in, const int* in_sizes, int n_in,
                              void* d_out, int out_size) {
    const float* x   = (const float*)d_in[0];
    const float* lc  = (const float*)d_in[1];
    const float* hc  = (const float*)d_in[2];
    const float* w1  = (const float*)d_in[3];
    const float* b1  = (const float*)d_in[4];
    const float* w2  = (const float*)d_in[5];
    const float* b2  = (const float*)d_in[6];
    const float* wl  = (const float*)d_in[7];
    const float* bl  = (const float*)d_in[8];
    const float* gl  = (const float*)d_in[9];
    const float* el  = (const float*)d_in[10];
    const float* wm  = (const float*)d_in[11];
    const float* bm  = (const float*)d_in[12];
    const float* gm  = (const float*)d_in[13];
    const float* em  = (const float*)d_in[14];
    const float* wh  = (const float*)d_in[15];
    const float* bh  = (const float*)d_in[16];
    const float* gh  = (const float*)d_in[17];
    const float* eh  = (const float*)d_in[18];
    const float* saw = (const float*)d_in[19];
    const float* sab = (const float*)d_in[20];
    float* out = (float*)d_out;

    static int smset = 0;
    if (!smset) {
        cudaFuncSetAttribute(k_conv, cudaFuncAttributeMaxDynamicSharedMemorySize, DYNSM);
        smset = 1;
    }

    k_wprep<<<dim3(20, 5, 3), 256>>>(wl, wm, wh);
    k_avg  <<<dim3(128, 40), 256>>>(x);
    k_ca   <<<128, 256>>>(w1, b1, w2, b2);
    k_prep <<<512, 256>>>(lc, hc);
    k_kmat <<<dim3(256, 2), 256>>>(0);
    k_band2<<<dim3(640, 2), 256>>>(x);
    k_high <<<10240, 256>>>(x);
    k_conv <<<dim3(5, 128, 3), 256, DYNSM>>>(x, bl, gl, el, bm, gm, em, bh, gh, eh);
    k_fuse <<<128, 256>>>(saw, sab, out);
}

// round 16
// speedup vs baseline: 6.2048x; 1.0652x over previous
#include <cuda_runtime.h>
#include <cuda_fp16.h>
#include <math.h>
#include <stdint.h>

#define SZ 10485760
__device__ float g_bands[3][SZ];     // low, mid, high
__device__ float g_feat[3][SZ];
__device__ float g_avg[40960];
__device__ float g_cw[128 * 960];
__device__ float g_kappa[2][256];
__device__ float g_part[4][32768];   // fuse partial dots
__device__ __align__(16) __half g_Wh[2764800];   // [m][cotile][chunk][tap][k16][co64]
__device__ __align__(16) __half g_Kh[2][65536];  // circulant K hi  [m][q][p]
__device__ __align__(16) __half g_Kl[2][65536];  // circulant K lo

__device__ __forceinline__ uint32_t s2u(const void* p) {
    uint32_t a;
    asm("{ .reg .u64 t; cvta.to.shared.u64 t, %1; cvt.u32.u64 %0, t; }" : "=r"(a) : "l"(p));
    return a;
}

// ---------------------------------------------------------------------------
__global__ void k_avg(const float* __restrict__ x) {
    int b = blockIdx.x;
    int c = blockIdx.y * 8 + (threadIdx.x >> 5);
    int lane = threadIdx.x & 31;
    const float* px = x + ((size_t)b * 320 + c) * 256;
    float s = 0.f;
#pragma unroll
    for (int i = 0; i < 8; i++) s += px[lane + 32 * i];
#pragma unroll
    for (int o = 16; o > 0; o >>= 1) s += __shfl_xor_sync(0xffffffffu, s, o);
    if (lane == 0) g_avg[b * 320 + c] = s * (1.0f / 256.0f);
}

__global__ void k_ca(const float* __restrict__ w1, const float* __restrict__ b1,
                     const float* __restrict__ w2, const float* __restrict__ b2) {
    __shared__ float av[320];
    __shared__ float hs[40];
    int b = blockIdx.x, tid = threadIdx.x;
    for (int e = tid; e < 320; e += 256) av[e] = g_avg[b * 320 + e];
    __syncthreads();
    if (tid < 40) {
        float s = b1[tid];
        for (int c = 0; c < 320; c++) s += av[c] * w1[tid * 320 + c];
        hs[tid] = fmaxf(s, 0.0f);
    }
    __syncthreads();
    for (int o = tid; o < 960; o += 256) {
        float s = b2[o];
#pragma unroll
        for (int k = 0; k < 40; k++) s += hs[k] * w2[o * 40 + k];
        g_cw[b * 960 + o] = 1.0f / (1.0f + expf(-s));
    }
}

__device__ __forceinline__ float jsig(float z) { return 1.0f / (1.0f + expf(-z)); }

// kappa: one block per (m, output); thread = one (u,v) term; double tree-reduce.
__global__ void k_prep(const float* __restrict__ lcp, const float* __restrict__ hcp) {
    __shared__ double ctab[16];
    __shared__ double red[256];
    int tid = threadIdx.x;
    if (tid < 16) ctab[tid] = cos((double)tid * 3.14159265358979323846 / 8.0);
    __syncthreads();
    float lc = *lcp, hc = *hcp;
    int bx = blockIdx.x;
    int m = bx >> 8, t = bx & 255;
    int a = t >> 4, bb = t & 15;
    int u = tid >> 4, v = tid & 15;
    float step = __fdiv_rn(2.0f, 15.0f);
    int s = (u + 8) & 15, t2 = (v + 8) & 15;
    float yv = __fadd_rn(__fmul_rn((float)s, step), -1.0f);
    float xv = __fadd_rn(__fmul_rn((float)t2, step), -1.0f);
    float d2 = __fadd_rn(__fmul_rn(xv, xv), __fmul_rn(yv, yv));
    float d = __fdiv_rn(__fsqrt_rn(d2), 1.4142135623730951f);
    float mv;
    if (m == 0) {
        mv = jsig(__fdiv_rn(__fsub_rn(lc, d), 1e-6f));
    } else {
        float m1 = jsig(__fdiv_rn(__fsub_rn(d, lc), 1e-6f));
        float m2 = jsig(__fdiv_rn(__fsub_rn(hc, d), 1e-6f));
        mv = m1 * m2;
    }
    int ph = (u * a + v * bb) & 15;
    red[tid] = (double)mv * ctab[ph];
    __syncthreads();
    for (int off = 128; off > 0; off >>= 1) {
        if (tid < off) red[tid] += red[tid + off];
        __syncthreads();
    }
    if (tid == 0) g_kappa[m][t] = (float)(red[0] * (1.0 / 256.0));
}

// circulant matrix K[q][p] (f16 hi/lo) from kappa
__global__ void k_kmat(int dummy) {
    int q = blockIdx.x, m = blockIdx.y, p = threadIdx.x;
    int aa = ((((p >> 4) - (q >> 4)) & 15) << 4) | (((p & 15) - (q & 15)) & 15);
    float val = g_kappa[m][aa];
    __half h = __float2half_rn(val);
    g_Kh[m][q * 256 + p] = h;
    g_Kl[m][q * 256 + p] = __float2half_rn(val - __half2float(h));
}

// ---------------------------------------------------------------------------
// band GEMM via mma.sync, hi/lo split (3 passes). grid (640, 2), block 256.
#define BA_AH 0
#define BA_AL 3072
#define BA_BH 6144
#define BA_BL 14592
#define BA_SM 23040

__global__ void __launch_bounds__(256, 2) k_band2(const float* __restrict__ x) {
    __shared__ char P[BA_SM];
    uint32_t Pu = s2u(P);
    int tid = threadIdx.x;
    int m = blockIdx.y;
    int rows0 = blockIdx.x * 64;
    int lane = tid & 31, wid = tid >> 5;
    int rw = wid & 3, nh = wid >> 2;

    float acc[16][4];
#pragma unroll
    for (int f = 0; f < 16; f++)
#pragma unroll
        for (int r = 0; r < 4; r++) acc[f][r] = 0.f;

    int arow = tid >> 2, aqg = (tid & 3) * 4;
    const uint32_t* Kh2 = (const uint32_t*)(const void*)g_Kh[m];
    const uint32_t* Kl2 = (const uint32_t*)(const void*)g_Kl[m];
    int bk = tid >> 7, bn2 = tid & 127;

    uint32_t aAddrH = Pu + BA_AH + (uint32_t)((rw * 16 + (lane & 15)) * 48) + ((lane >> 4) * 16);
    uint32_t aAddrL = aAddrH + (BA_AL - BA_AH);

    for (int kc = 0; kc < 16; kc++) {
        int q0 = kc * 16;
        __syncthreads();
        {   // A tile 64x16 f32 -> hi/lo f16
            float4 v = *(const float4*)(x + (size_t)(rows0 + arow) * 256 + q0 + aqg);
            __half hx = __float2half_rn(v.x), hy = __float2half_rn(v.y);
            __half hz = __float2half_rn(v.z), hw = __float2half_rn(v.w);
            uint2 hv, lv;
            hv.x = (uint32_t)__half_as_ushort(hx) | ((uint32_t)__half_as_ushort(hy) << 16);
            hv.y = (uint32_t)__half_as_ushort(hz) | ((uint32_t)__half_as_ushort(hw) << 16);
            __half lx = __float2half_rn(v.x - __half2float(hx));
            __half ly = __float2half_rn(v.y - __half2float(hy));
            __half lz = __float2half_rn(v.z - __half2float(hz));
            __half lw = __float2half_rn(v.w - __half2float(hw));
            lv.x = (uint32_t)__half_as_ushort(lx) | ((uint32_t)__half_as_ushort(ly) << 16);
            lv.y = (uint32_t)__half_as_ushort(lz) | ((uint32_t)__half_as_ushort(lw) << 16);
            *(uint2*)(P + BA_AH + arow * 48 + aqg * 2) = hv;
            *(uint2*)(P + BA_AL + arow * 48 + aqg * 2) = lv;
        }
        {   // B tile 16x256 f16 hi/lo from precomputed K
#pragma unroll
            for (int kk = 0; kk < 8; kk++) {
                int k = kk * 2 + bk;
                uint32_t vh = Kh2[(q0 + k) * 128 + bn2];
                uint32_t vl = Kl2[(q0 + k) * 128 + bn2];
                *(uint32_t*)(P + BA_BH + k * 528 + bn2 * 4) = vh;
                *(uint32_t*)(P + BA_BL + k * 528 + bn2 * 4) = vl;
            }
        }
        __syncthreads();
        uint32_t ah0, ah1, ah2, ah3, al0, al1, al2, al3;
        asm volatile("ldmatrix.sync.aligned.m8n8.x4.shared.b16 {%0,%1,%2,%3}, [%4];"
                     : "=r"(ah0), "=r"(ah1), "=r"(ah2), "=r"(ah3) : "r"(aAddrH));
        asm volatile("ldmatrix.sync.aligned.m8n8.x4.shared.b16 {%0,%1,%2,%3}, [%4];"
                     : "=r"(al0), "=r"(al1), "=r"(al2), "=r"(al3) : "r"(aAddrL));
#pragma unroll
        for (int nb = 0; nb < 8; nb++) {
            int n16 = nh * 128 + nb * 16;
            uint32_t bAddr = Pu + BA_BH + (uint32_t)((lane & 15) * 528 + n16 * 2 + (lane >> 4) * 16);
            uint32_t bh0, bh1, bh2, bh3, bl0, bl1, bl2, bl3;
            asm volatile("ldmatrix.sync.aligned.m8n8.x4.trans.shared.b16 {%0,%1,%2,%3}, [%4];"
                         : "=r"(bh0), "=r"(bh1), "=r"(bh2), "=r"(bh3) : "r"(bAddr));
            asm volatile("ldmatrix.sync.aligned.m8n8.x4.trans.shared.b16 {%0,%1,%2,%3}, [%4];"
                         : "=r"(bl0), "=r"(bl1), "=r"(bl2), "=r"(bl3)
                         : "r"(bAddr + (uint32_t)(BA_BL - BA_BH)));
            float* A0 = acc[2 * nb];
            float* A1 = acc[2 * nb + 1];
#define BMMA(AC, x0, x1, x2, x3, y0, y1)                                      \
            asm volatile("mma.sync.aligned.m16n8k16.row.col.f32.f16.f16.f32 " \
                "{%0,%1,%2,%3}, {%4,%5,%6,%7}, {%8,%9}, {%0,%1,%2,%3};"       \
                : "+f"((AC)[0]), "+f"((AC)[1]), "+f"((AC)[2]), "+f"((AC)[3])  \
                : "r"(x0), "r"(x1), "r"(x2), "r"(x3), "r"(y0), "r"(y1))
            BMMA(A0, ah0, ah1, ah2, ah3, bh0, bh1);
            BMMA(A0, ah0, ah1, ah2, ah3, bl0, bl1);
            BMMA(A0, al0, al1, al2, al3, bh0, bh1);
            BMMA(A1, ah0, ah1, ah2, ah3, bh2, bh3);
            BMMA(A1, ah0, ah1, ah2, ah3, bl2, bl3);
            BMMA(A1, al0, al1, al2, al3, bh2, bh3);
#undef BMMA
        }
    }
    float* outp = g_bands[m];
    int row = rows0 + rw * 16 + (lane >> 2);
#pragma unroll
    for (int f = 0; f < 16; f++) {
        int p0 = nh * 128 + f * 8 + (lane & 3) * 2;
        *(float2*)(outp + (size_t)row * 256 + p0) = make_float2(acc[f][0], acc[f][1]);
        *(float2*)(outp + (size_t)(row + 8) * 256 + p0) = make_float2(acc[f][2], acc[f][3]);
    }
}

__global__ void k_high(const float* __restrict__ x) {
    size_t i = (size_t)blockIdx.x * 256 + threadIdx.x;
    float4 xv = ((const float4*)x)[i];
    float4 b0 = ((const float4*)g_bands[0])[i];
    float4 b1 = ((const float4*)g_bands[1])[i];
    float4 r;
    r.x = xv.x - b0.x - b1.x; r.y = xv.y - b0.y - b1.y;
    r.z = xv.z - b0.z - b1.z; r.w = xv.w - b0.w - b1.w;
    ((float4*)g_bands[2])[i] = r;
}

// weight prep: f32 -> f16 blocks [m][cotile][chunk][tap][k16][co64]
__global__ void k_wprep(const float* __restrict__ wl, const float* __restrict__ wm,
                        const float* __restrict__ wh) {
    int chunk = blockIdx.x, cotile = blockIdx.y, m = blockIdx.z;
    const float* W = (m == 0) ? wl : ((m == 1) ? wm : wh);
    size_t base = ((size_t)(m * 5 + cotile) * 20 + chunk) * 9216;
    for (int i = threadIdx.x; i < 9216; i += 256) {
        int co = i & 63, k = (i >> 6) & 15, tap = i >> 10;
        float w = W[(size_t)(cotile * 64 + co) * 2880 + (chunk * 16 + k) * 9 + tap];
        g_Wh[base + (size_t)tap * 1024 + k * 64 + co] = __float2half_rn(w);
    }
}

// ---------------------------------------------------------------------------
// double-buffered f16 mma.sync conv + bias + GroupNorm + affine + residual.
// grid (5 cotile, 128 b, 3 m), block 256 (8 warps).
// X smem x2: [324 px][16 ci] f16, 48B pitch.  W smem x2: 144 rows x 144B pitch.
#define XH0 0
#define XH1 15552
#define WS0 31104
#define WS1 51840
#define REDOF 72576
#define STAOF 74624
#define DYNSM 74688

__global__ void __launch_bounds__(256, 2) k_conv(
    const float* __restrict__ x,
    const float* __restrict__ bl, const float* __restrict__ gl, const float* __restrict__ el,
    const float* __restrict__ bm, const float* __restrict__ gm, const float* __restrict__ em,
    const float* __restrict__ bh, const float* __restrict__ gh, const float* __restrict__ eh) {
    extern __shared__ char P[];
    uint32_t Pu = s2u(P);
    int tid = threadIdx.x;
    int cotile = blockIdx.x, b = blockIdx.y, m = blockIdx.z;
    const float* biasp = (m == 0) ? bl : ((m == 1) ? bm : bh);
    const float* gamp  = (m == 0) ? gl : ((m == 1) ? gm : gh);
    const float* betp  = (m == 0) ? el : ((m == 1) ? em : eh);
    const float* src = g_bands[m];

    // zero both X buffers (borders stay zero forever)
    for (int i = tid * 16; i < 31104; i += 4096)
        *(uint4*)(P + i) = make_uint4(0, 0, 0, 0);

    int lane = tid & 31, wid = tid >> 5;
    int wq = wid & 3, chh = wid >> 2;
    uint32_t laneAoff[4];
#pragma unroll
    for (int mf = 0; mf < 4; mf++)
        laneAoff[mf] = (uint32_t)(((wq * 4 + mf) * 18 + (lane & 15)) * 48) + ((lane >> 4) * 16);

    float acc[4][4][4];
#pragma unroll
    for (int a = 0; a < 4; a++)
#pragma unroll
        for (int n = 0; n < 4; n++)
#pragma unroll
            for (int r = 0; r < 4; r++) acc[a][n][r] = 0.f;

    const size_t bimg = (size_t)b * 81920;
    const uint4* wblock = (const uint4*)(const void*)(g_Wh +
        ((size_t)(m * 5 + cotile) * 20) * 9216);

    int xr0 = tid >> 4, xc0 = tid & 15;
    uint32_t xrowb = (uint32_t)(((xr0 + 1) * 18 + (xc0 + 1)) * 48);

    float xr[16];
    uint4 wr0, wr1, wr2, wr3, wr4;

#define LOADSTAGE(cc)                                                         \
    {                                                                         \
        const float* sp = src + bimg + (size_t)(cc) * 4096 + tid;             \
        _Pragma("unroll")                                                     \
        for (int j = 0; j < 16; j++) xr[j] = sp[(size_t)j * 256];             \
        const uint4* ws = wblock + (size_t)(cc) * 1152;                       \
        wr0 = ws[tid]; wr1 = ws[tid + 256]; wr2 = ws[tid + 512];              \
        wr3 = ws[tid + 768];                                                  \
        if (tid < 128) wr4 = ws[tid + 1024];                                  \
    }
#define STORESTAGE(xb, wb)                                                    \
    {                                                                         \
        uint32_t hv[8];                                                       \
        _Pragma("unroll")                                                     \
        for (int j = 0; j < 8; j++)                                           \
            hv[j] = (uint32_t)__half_as_ushort(__float2half_rn(xr[2 * j])) |  \
                    ((uint32_t)__half_as_ushort(__float2half_rn(xr[2 * j + 1])) << 16); \
        *(uint4*)(P + (xb) + xrowb)      = make_uint4(hv[0], hv[1], hv[2], hv[3]); \
        *(uint4*)(P + (xb) + xrowb + 16) = make_uint4(hv[4], hv[5], hv[6], hv[7]); \
        *(uint4*)(P + (wb) + ((tid) >> 3) * 144 + ((tid) & 7) * 16) = wr0;    \
        *(uint4*)(P + (wb) + ((tid + 256) >> 3) * 144 + ((tid + 256) & 7) * 16) = wr1; \
        *(uint4*)(P + (wb) + ((tid + 512) >> 3) * 144 + ((tid + 512) & 7) * 16) = wr2; \
        *(uint4*)(P + (wb) + ((tid + 768) >> 3) * 144 + ((tid + 768) & 7) * 16) = wr3; \
        if (tid < 128)                                                        \
            *(uint4*)(P + (wb) + ((tid + 1024) >> 3) * 144 + ((tid + 1024) & 7) * 16) = wr4; \
    }

    LOADSTAGE(0);
    STORESTAGE(XH0, WS0);
    __syncthreads();

    for (int c = 0; c < 20; c++) {
        int cur = c & 1;
        uint32_t xb = cur ? XH1 : XH0;
        uint32_t wb = cur ? WS1 : WS0;
        if (c < 19) LOADSTAGE(c + 1);
#pragma unroll
        for (int tap = 0; tap < 9; tap++) {
            uint32_t aoff = (uint32_t)(((tap / 3) * 18 + (tap % 3)) * 48);
            uint32_t bf[4][2];
#pragma unroll
            for (int t16 = 0; t16 < 2; t16++) {
                uint32_t baddr = Pu + wb + (uint32_t)(tap * 2304 +
                    (lane & 15) * 144 + (chh * 32 + t16 * 16) * 2 + (lane >> 4) * 16);
                uint32_t r0, r1, r2, r3;
                asm volatile(
                    "ldmatrix.sync.aligned.m8n8.x4.trans.shared.b16 {%0,%1,%2,%3}, [%4];"
                    : "=r"(r0), "=r"(r1), "=r"(r2), "=r"(r3) : "r"(baddr));
                bf[t16 * 2][0] = r0; bf[t16 * 2][1] = r1;
                bf[t16 * 2 + 1][0] = r2; bf[t16 * 2 + 1][1] = r3;
            }
#pragma unroll
            for (int mf = 0; mf < 4; mf++) {
                uint32_t a0, a1, a2, a3;
                asm volatile(
                    "ldmatrix.sync.aligned.m8n8.x4.shared.b16 {%0,%1,%2,%3}, [%4];"
                    : "=r"(a0), "=r"(a1), "=r"(a2), "=r"(a3)
                    : "r"(Pu + xb + laneAoff[mf] + aoff));
#pragma unroll
                for (int nf = 0; nf < 4; nf++)
                    asm volatile(
                        "mma.sync.aligned.m16n8k16.row.col.f32.f16.f16.f32 "
                        "{%0,%1,%2,%3}, {%4,%5,%6,%7}, {%8,%9}, {%0,%1,%2,%3};"
                        : "+f"(acc[mf][nf][0]), "+f"(acc[mf][nf][1]),
                          "+f"(acc[mf][nf][2]), "+f"(acc[mf][nf][3])
                        : "r"(a0), "r"(a1), "r"(a2), "r"(a3),
                          "r"(bf[nf][0]), "r"(bf[nf][1]));
            }
        }
        if (c < 19) {
            uint32_t xb2 = cur ? XH0 : XH1;
            uint32_t wb2 = cur ? WS0 : WS1;
            STORESTAGE(xb2, wb2);
        }
        __syncthreads();
    }

    // ---- epilogue ----
    int co_base = cotile * 64 + chh * 32;
    float bias2[4][2];
#pragma unroll
    for (int nf = 0; nf < 4; nf++) {
        int co0 = co_base + nf * 8 + 2 * (lane & 3);
        bias2[nf][0] = biasp[co0];
        bias2[nf][1] = biasp[co0 + 1];
    }
    float s = 0.f, q = 0.f;
#pragma unroll
    for (int mf = 0; mf < 4; mf++)
#pragma unroll
        for (int nf = 0; nf < 4; nf++)
#pragma unroll
            for (int r = 0; r < 4; r++) {
                float v = acc[mf][nf][r] + bias2[nf][r & 1];
                s += v; q += v * v;
            }
    float* red_s = (float*)(P + REDOF);
    float* red_q = red_s + 256;
    red_s[tid] = s; red_q[tid] = q;
    __syncthreads();
    for (int off = 128; off > 0; off >>= 1) {
        if (tid < off) { red_s[tid] += red_s[tid + off]; red_q[tid] += red_q[tid + off]; }
        __syncthreads();
    }
    float* stat = (float*)(P + STAOF);
    if (tid == 0) {
        float mu = red_s[0] * (1.f / 16384.f);
        float var = red_q[0] * (1.f / 16384.f) - mu * mu;
        stat[0] = mu;
        stat[1] = rsqrtf(var + 1e-5f);
    }
    __syncthreads();
    float mu = stat[0], rs = stat[1];
    float* feat = g_feat[m];
#pragma unroll
    for (int nf = 0; nf < 4; nf++) {
        int co0 = co_base + nf * 8 + 2 * (lane & 3);
        float ga0 = gamp[co0], be0 = betp[co0];
        float ga1 = gamp[co0 + 1], be1 = betp[co0 + 1];
#pragma unroll
        for (int mf = 0; mf < 4; mf++) {
            int px0 = wq * 64 + mf * 16 + (lane >> 2);
#pragma unroll
            for (int r = 0; r < 4; r++) {
                int px = px0 + ((r >= 2) ? 8 : 0);
                int co = co0 + (r & 1);
                float v = acc[mf][nf][r] + bias2[nf][r & 1];
                float ga = (r & 1) ? ga1 : ga0;
                float be = (r & 1) ? be1 : be0;
                size_t o = bimg + (size_t)co * 256 + px;
                feat[o] = (v - mu) * rs * ga + be + x[o];
            }
        }
    }
}

// ---------------------------------------------------------------------------
// fuse split: k_dot computes partial channel dots, k_out applies sigmoid gate.
__global__ void k_dot(const float* __restrict__ saw) {
    __shared__ float cw_s[960];
    __shared__ float saw_s[320];
    int b = blockIdx.x, cs = blockIdx.y, p = threadIdx.x;
    for (int e = p; e < 960; e += 256) cw_s[e] = g_cw[b * 960 + e];
    for (int e = p; e < 320; e += 256) saw_s[e] = saw[e];
    __syncthreads();
    size_t base = (size_t)b * 81920 + p;
    float sacc = 0.f;
    int c0 = cs * 80;
    for (int c = c0; c < c0 + 80; c++) {
        size_t o = base + (size_t)c * 256;
        float f = cw_s[c] * g_feat[0][o] + cw_s[320 + c] * g_feat[1][o]
                + cw_s[640 + c] * g_feat[2][o];
        sacc += f * saw_s[c];
    }
    g_part[cs][b * 256 + p] = sacc;
}

__global__ void k_out(const float* __restrict__ sab, float* __restrict__ out) {
    __shared__ float cw_s[960];
    int b = blockIdx.x, cs = blockIdx.y, p = threadIdx.x;
    for (int e = p; e < 960; e += 256) cw_s[e] = g_cw[b * 960 + e];
    __syncthreads();
    int i = b * 256 + p;
    float sacc = g_part[0][i] + g_part[1][i] + g_part[2][i] + g_part[3][i];
    float sw = 1.0f / (1.0f + expf(-(sacc + sab[0])));
    size_t base = (size_t)b * 81920 + p;
    int c0 = cs * 80;
    for (int c = c0; c < c0 + 80; c++) {
        size_t o = base + (size_t)c * 256;
        float f = cw_s[c] * g_feat[0][o] + cw_s[320 + c] * g_feat[1][o]
                + cw_s[640 + c] * g_feat[2][o];
        out[o] = f * sw;
    }
}

// ---------------------------------------------------------------------------
extern "C" void kernel_launch(void* const* d_in, const int* in_sizes, int n_in,
                              void* d_out, int out_size) {
    const float* x   = (const float*)d_in[0];
    const float* lc  = (const float*)d_in[1];
    const float* hc  = (const float*)d_in[2];
    const float* w1  = (const float*)d_in[3];
    const float* b1  = (const float*)d_in[4];
    const float* w2  = (const float*)d_in[5];
    const float* b2  = (const float*)d_in[6];
    const float* wl  = (const float*)d_in[7];
    const float* bl  = (const float*)d_in[8];
    const float* gl  = (const float*)d_in[9];
    const float* el  = (const float*)d_in[10];
    const float* wm  = (const float*)d_in[11];
    const float* bm  = (const float*)d_in[12];
    const float* gm  = (const float*)d_in[13];
    const float* em  = (const float*)d_in[14];
    const float* wh  = (const float*)d_in[15];
    const float* bh  = (const float*)d_in[16];
    const float* gh  = (const float*)d_in[17];
    const float* eh  = (const float*)d_in[18];
    const float* saw = (const float*)d_in[19];
    const float* sab = (const float*)d_in[20];
    float* out = (float*)d_out;

    static int smset = 0;
    if (!smset) {
        cudaFuncSetAttribute(k_conv, cudaFuncAttributeMaxDynamicSharedMemorySize, DYNSM);
        smset = 1;
    }

    k_wprep<<<dim3(20, 5, 3), 256>>>(wl, wm, wh);
    k_avg  <<<dim3(128, 40), 256>>>(x);
    k_ca   <<<128, 256>>>(w1, b1, w2, b2);
    k_prep <<<512, 256>>>(lc, hc);
    k_kmat <<<dim3(256, 2), 256>>>(0);
    k_band2<<<dim3(640, 2), 256>>>(x);
    k_high <<<10240, 256>>>(x);
    k_conv <<<dim3(5, 128, 3), 256, DYNSM>>>(x, bl, gl, el, bm, gm, em, bh, gh, eh);
    k_dot  <<<dim3(128, 4), 256>>>(saw);
    k_out  <<<dim3(128, 4), 256>>>(sab, out);
}